// round 12
// baseline (speedup 1.0000x reference)
#include <cuda_runtime.h>
#include <cuda_fp16.h>
#include <cstdint>

#define D_DIM 512
#define C_DIM 1024
#define M_TILE 64
#define NTHREADS 256

// smem layout (bytes)
#define QOFF   0            // 64 x 512 fp16 raw-q (8 panels SW128); GEMM2 stages 0,1
#define WOFF   65536        // W: 16 panels (64r x 128B) SW128; ALSO GEMM1 even-kc B stages
#define SBOFF  196608       // GEMM1 odd-kc B stage; GEMM2 stage 2 (32KB)
#define REDOFF 229376       // 256 floats
#define INVOFF 230400       // 64 floats
#define SMEM_BYTES 230656
#define ST2SZ  32768

// ---- small device scratch (3 MiB) ----
__device__ __half g_Kh[C_DIM * D_DIM];   // normalized keys fp16
__device__ __half g_Vt[C_DIM * C_DIM];   // val transposed fp16: g_Vt[n*C+k] = val[k*C+n]

// ---- helpers ----
__device__ __forceinline__ uint32_t smem_u32(const void* p) {
    uint32_t a;
    asm("{ .reg .u64 t; cvta.to.shared.u64 t, %1; cvt.u32.u64 %0, t; }" : "=r"(a) : "l"(p));
    return a;
}
#define SWZ(x) ((x) ^ (((x) >> 3) & 0x70))

__device__ __forceinline__ void cp16(uint32_t s, const void* g) {
    asm volatile("cp.async.cg.shared.global [%0], [%1], 16;" :: "r"(s), "l"(g));
}
#define CP_COMMIT() asm volatile("cp.async.commit_group;" ::: "memory")
#define CP_WAIT1()  asm volatile("cp.async.wait_group 1;" ::: "memory")
#define CP_WAIT0()  asm volatile("cp.async.wait_group 0;" ::: "memory")

__device__ __forceinline__ void ldsm4(unsigned r[4], uint32_t a) {
    asm volatile("ldmatrix.sync.aligned.m8n8.x4.shared.b16 {%0,%1,%2,%3}, [%4];"
                 : "=r"(r[0]), "=r"(r[1]), "=r"(r[2]), "=r"(r[3]) : "r"(a));
}
__device__ __forceinline__ void mma16816(float c[4], const unsigned a[4], const unsigned b[2]) {
    asm volatile(
        "mma.sync.aligned.m16n8k16.row.col.f32.f16.f16.f32 "
        "{%0,%1,%2,%3}, {%4,%5,%6,%7}, {%8,%9}, {%0,%1,%2,%3};\n"
        : "+f"(c[0]), "+f"(c[1]), "+f"(c[2]), "+f"(c[3])
        : "r"(a[0]), "r"(a[1]), "r"(a[2]), "r"(a[3]), "r"(b[0]), "r"(b[1]));
}

// sharp(x) = sigmoid(10x-5) + sigmoid(-10x-5)
__device__ __forceinline__ float sharp_fn(float x) {
    const float E = 148.4131591f;      // e^5
    const float E2p1 = 22027.4658f;    // e^10 + 1
    float u = __expf(10.f * x);
    float eu = E * u;
    float num = fmaf(eu, u, fmaf(2.f, u, E));
    float den = fmaf(eu, u, fmaf(E2p1, u, E));
    return __fdividef(num, den);
}

// fill: 256 rows x 64 cols fp16; pg = per-thread global ptr, sdst = dst + thread smem const
template <int LDB>
__device__ __forceinline__ void fillB2p(const __half* __restrict__ pg, uint32_t sdst) {
#pragma unroll
    for (int it = 0; it < 8; ++it)
        cp16(sdst + it * 4096, pg + (size_t)it * 32 * LDB);
}

// fragment loader with precomputed bases: addr = sX + row_base + koff[ks]  (1 IADD3 each)
__device__ __forceinline__ void load_fr2p(uint32_t sA, uint32_t sB, uint32_t ko,
                                          const uint32_t arow[2], const uint32_t brow[4],
                                          unsigned a[2][4], unsigned b[8][2]) {
#pragma unroll
    for (int mi = 0; mi < 2; ++mi)
        ldsm4(a[mi], sA + arow[mi] + ko);
#pragma unroll
    for (int pr = 0; pr < 4; ++pr) {
        unsigned r4[4];
        ldsm4(r4, sB + brow[pr] + ko);
        b[pr * 2][0] = r4[0]; b[pr * 2 + 1][0] = r4[1];
        b[pr * 2][1] = r4[2]; b[pr * 2 + 1][1] = r4[3];
    }
}

// ---- merged prep kernel ----
__global__ void prep_kernel(const float* __restrict__ key, const float* __restrict__ val) {
    __shared__ float tile[32][33];
    __shared__ float ws[8];
    __shared__ float sinv;
    const int tid = threadIdx.x;
    if (blockIdx.x < 1024) {
        const int ko = (blockIdx.x & 31) * 32;
        const int no = (blockIdx.x >> 5) * 32;
        const int tx = tid & 31, ty = tid >> 5;
#pragma unroll
        for (int j = 0; j < 32; j += 8)
            tile[ty + j][tx] = val[(size_t)(ko + ty + j) * C_DIM + no + tx];
        __syncthreads();
#pragma unroll
        for (int j = 0; j < 32; j += 8)
            g_Vt[(size_t)(no + ty + j) * C_DIM + ko + tx] = __float2half(tile[tx][ty + j]);
    } else {
        const int r = blockIdx.x - 1024;
        const float* kr = key + (size_t)r * D_DIM;
        float v[2];
        float ss = 0.f;
#pragma unroll
        for (int i = 0; i < 2; ++i) { v[i] = kr[tid + i * 256]; ss += v[i] * v[i]; }
#pragma unroll
        for (int o = 16; o > 0; o >>= 1) ss += __shfl_down_sync(0xffffffffu, ss, o);
        if ((tid & 31) == 0) ws[tid >> 5] = ss;
        __syncthreads();
        if (tid == 0) {
            float s = 0.f;
#pragma unroll
            for (int j = 0; j < 8; ++j) s += ws[j];
            sinv = rsqrtf(s + 1e-12f);
        }
        __syncthreads();
        const float iv = sinv;
#pragma unroll
        for (int i = 0; i < 2; ++i)
            g_Kh[(size_t)r * D_DIM + tid + i * 256] = __float2half(v[i] * iv);
    }
}

// ---- fused main kernel: 256 threads, 8 warps, warp tile 32x64 ----
__global__ __launch_bounds__(NTHREADS, 1)
void fused_kv_kernel(const float* __restrict__ query, float* __restrict__ out) {
    extern __shared__ char smem[];
    const uint32_t sb = smem_u32(smem);
    float* red = (float*)(smem + REDOFF);
    float* inv = (float*)(smem + INVOFF);

    const int tid  = threadIdx.x;
    const int lane = tid & 31;
    const int wid  = tid >> 5;
    const int wm   = wid >> 2;
    const int wn   = wid & 3;
    const int g    = lane >> 2;
    const int tig  = lane & 3;
    const int lrow = lane & 15;
    const int hs   = lane >> 4;
    const int row0 = blockIdx.x * M_TILE;

    // ---- precomputed LDSM address components ----
    // SWZ(row*128 + ks*32 + hs*16) = row*128 + ((ks*32 + hs*16) ^ ((row&7)*16)); row&7 == lrow&7
    uint32_t koff[4], arow[2], brow[4];
    {
        const uint32_t xr = (uint32_t)(lrow & 7) * 16u;
#pragma unroll
        for (int ks = 0; ks < 4; ++ks)
            koff[ks] = ((uint32_t)(ks * 32 + hs * 16)) ^ xr;
#pragma unroll
        for (int mi = 0; mi < 2; ++mi)
            arow[mi] = (uint32_t)(wm * 32 + mi * 16 + lrow) * 128u;
#pragma unroll
        for (int pr = 0; pr < 4; ++pr)
            brow[pr] = (uint32_t)(wn * 64 + pr * 16 + lrow) * 128u;
    }
    // fill constants: smem const and per-thread global element offsets
    const uint32_t fr0 = (uint32_t)(tid >> 3);
    const uint32_t fc  = (uint32_t)(tid & 7);
    const uint32_t fs0 = fr0 * 128u + ((fc * 16u) ^ ((fr0 & 7u) * 16u));
    const uint32_t gofs1 = fr0 * D_DIM + fc * 8;   // stride D_DIM source
    const uint32_t gofs2 = fr0 * C_DIM + fc * 8;   // stride C_DIM source

    // ---- Step 0: load RAW q -> fp16 smem (swizzled) + 1/||q|| ----
    {
        const int r = tid >> 2;
        const int p = tid & 3;
        const float* qrow = query + (size_t)(row0 + r) * D_DIM + p * 128;
        float ss = 0.f;
#pragma unroll
        for (int q = 0; q < 2; ++q) {
            char* pb = smem + QOFF + (2 * p + q) * 8192;
#pragma unroll 4
            for (int j = 0; j < 64; j += 4) {
                float4 v = *(const float4*)(qrow + q * 64 + j);
                ss += v.x * v.x + v.y * v.y + v.z * v.z + v.w * v.w;
                int b = r * 128 + j * 2;
                *(__half2*)(pb + SWZ(b))     = __floats2half2_rn(v.x, v.y);
                *(__half2*)(pb + SWZ(b + 4)) = __floats2half2_rn(v.z, v.w);
            }
        }
        red[tid] = ss;
        __syncthreads();
        if (tid < M_TILE)
            inv[tid] = rsqrtf(red[tid * 4] + red[tid * 4 + 1] +
                              red[tid * 4 + 2] + red[tid * 4 + 3] + 1e-12f);
        __syncthreads();
    }
    float qa[4];
#pragma unroll
    for (int j = 0; j < 4; ++j) qa[j] = inv[wm * 32 + j * 8 + g];
    __syncthreads();
    if (tid < M_TILE) red[tid] = 0.f;

    // ---- GEMM1: W = sharp(qinv * (q @ Kn^T)); 32 iters (4 nc x 8 kc) ----
    {
        float acc[2][8][4];
        float rs[2][2] = {{0.f, 0.f}, {0.f, 0.f}};
        fillB2p<D_DIM>(g_Kh + gofs1, sb + WOFF + fs0);
        CP_COMMIT();

#pragma unroll 1
        for (int t = 0; t < 32; ++t) {
            const int nc = t >> 3, kc = t & 7;
            CP_WAIT0();
            __syncthreads();
            if (t + 1 < 32) {
                const int u = t + 1;
                const uint32_t dst = (u & 1) ? (uint32_t)SBOFF
                                             : (uint32_t)(WOFF + ((u >> 3) << 15));
                fillB2p<D_DIM>(g_Kh + ((size_t)(u >> 3) * 256) * D_DIM + (u & 7) * 64 + gofs1,
                               sb + dst + fs0);
                CP_COMMIT();
            }
            if (kc == 0) {
#pragma unroll
                for (int mi = 0; mi < 2; ++mi)
#pragma unroll
                    for (int ni = 0; ni < 8; ++ni)
#pragma unroll
                        for (int e = 0; e < 4; ++e) acc[mi][ni][e] = 0.f;
            }
            const uint32_t sB = sb + ((t & 1) ? (uint32_t)SBOFF
                                              : (uint32_t)(WOFF + (nc << 15)));
            const uint32_t sA = sb + QOFF + kc * 8192;

            unsigned a[2][2][4], b[2][8][2];
            load_fr2p(sA, sB, koff[0], arow, brow, a[0], b[0]);
#pragma unroll
            for (int ks = 0; ks < 4; ++ks) {
                const int cur = ks & 1;
                if (ks < 3)
                    load_fr2p(sA, sB, koff[ks + 1], arow, brow, a[cur ^ 1], b[cur ^ 1]);
#pragma unroll
                for (int mi = 0; mi < 2; ++mi)
#pragma unroll
                    for (int ni = 0; ni < 8; ++ni)
                        mma16816(acc[mi][ni], a[cur][mi], b[cur][ni]);
            }
            if (kc == 7) {
#pragma unroll
                for (int mi = 0; mi < 2; ++mi) {
#pragma unroll
                    for (int ni = 0; ni < 8; ++ni) {
                        int rr = wm * 32 + mi * 16 + g;
                        int cc = nc * 256 + wn * 64 + ni * 8 + tig * 2;
                        int panel = cc >> 6, c6 = cc & 63;
                        char* base = smem + WOFF + panel * 8192;
                        float w0 = sharp_fn(acc[mi][ni][0] * qa[mi * 2]);
                        float w1 = sharp_fn(acc[mi][ni][1] * qa[mi * 2]);
                        float w2 = sharp_fn(acc[mi][ni][2] * qa[mi * 2 + 1]);
                        float w3 = sharp_fn(acc[mi][ni][3] * qa[mi * 2 + 1]);
                        rs[mi][0] += w0 + w1;
                        rs[mi][1] += w2 + w3;
                        *(__half2*)(base + SWZ(rr * 128 + c6 * 2)) = __floats2half2_rn(w0, w1);
                        *(__half2*)(base + SWZ((rr + 8) * 128 + c6 * 2)) = __floats2half2_rn(w2, w3);
                    }
                }
            }
        }
        atomicAdd(&red[wm * 32 + g],       rs[0][0]);
        atomicAdd(&red[wm * 32 + g + 8],   rs[0][1]);
        atomicAdd(&red[wm * 32 + 16 + g],  rs[1][0]);
        atomicAdd(&red[wm * 32 + 24 + g],  rs[1][1]);
        __syncthreads();
        if (tid < M_TILE) inv[tid] = 1.f / red[tid];
        __syncthreads();
    }

    // ---- GEMM2: out = (1/rowsum) * W @ val; 64 iters (4 nc x 16 kc), 3 rotating stages ----
    {
        float acc[2][8][4];
        uint32_t s0 = QOFF, s1 = QOFF + ST2SZ, s2 = SBOFF;   // t, t+1, t+2 stage offsets
        fillB2p<C_DIM>(g_Vt + gofs2, sb + s0 + fs0);
        CP_COMMIT();
        fillB2p<C_DIM>(g_Vt + 64 + gofs2, sb + s1 + fs0);
        CP_COMMIT();

#pragma unroll 1
        for (int t = 0; t < 64; ++t) {
            const int nc = t >> 4, kc = t & 15;
            CP_WAIT1();
            __syncthreads();
            {
                const int u = t + 2;
                if (u < 64) {
                    fillB2p<C_DIM>(g_Vt + ((size_t)(u >> 4) * 256) * C_DIM + (u & 15) * 64 + gofs2,
                                   sb + s2 + fs0);
                    CP_COMMIT();
                }
            }
            if (kc == 0) {
#pragma unroll
                for (int mi = 0; mi < 2; ++mi)
#pragma unroll
                    for (int ni = 0; ni < 8; ++ni)
#pragma unroll
                        for (int e = 0; e < 4; ++e) acc[mi][ni][e] = 0.f;
            }
            const uint32_t sB = sb + s0;
            const uint32_t sA = sb + WOFF + kc * 8192;

            unsigned a[2][2][4], b[2][8][2];
            load_fr2p(sA, sB, koff[0], arow, brow, a[0], b[0]);
#pragma unroll
            for (int ks = 0; ks < 4; ++ks) {
                const int cur = ks & 1;
                if (ks < 3)
                    load_fr2p(sA, sB, koff[ks + 1], arow, brow, a[cur ^ 1], b[cur ^ 1]);
#pragma unroll
                for (int mi = 0; mi < 2; ++mi)
#pragma unroll
                    for (int ni = 0; ni < 8; ++ni)
                        mma16816(acc[mi][ni], a[cur][mi], b[cur][ni]);
            }
            if (kc == 15) {
#pragma unroll
                for (int mi = 0; mi < 2; ++mi) {
#pragma unroll
                    for (int ni = 0; ni < 8; ++ni) {
                        int rr = wm * 32 + mi * 16 + g;
                        int cc = nc * 256 + wn * 64 + ni * 8 + tig * 2;
                        float i0 = inv[rr], i8 = inv[rr + 8];
                        *(float2*)(out + (size_t)(row0 + rr) * C_DIM + cc) =
                            make_float2(acc[mi][ni][0] * i0, acc[mi][ni][1] * i0);
                        *(float2*)(out + (size_t)(row0 + rr + 8) * C_DIM + cc) =
                            make_float2(acc[mi][ni][2] * i8, acc[mi][ni][3] * i8);
                    }
                }
            }
            // rotate stages
            const uint32_t tmp = s0; s0 = s1; s1 = s2; s2 = tmp;
        }
    }
}

// ---------------------------------------------------------------------------
extern "C" void kernel_launch(void* const* d_in, const int* in_sizes, int n_in,
                              void* d_out, int out_size) {
    const float* query = (const float*)d_in[0];
    const float* key   = (const float*)d_in[1];
    const float* val   = (const float*)d_in[2];
    float* out = (float*)d_out;

    const int B = in_sizes[0] / D_DIM;

    prep_kernel<<<2048, 256>>>(key, val);

    cudaFuncSetAttribute(fused_kv_kernel,
                         cudaFuncAttributeMaxDynamicSharedMemorySize, SMEM_BYTES);
    fused_kv_kernel<<<B / M_TILE, NTHREADS, SMEM_BYTES>>>(query, out);
}

// round 13
// speedup vs baseline: 1.0211x; 1.0211x over previous
#include <cuda_runtime.h>
#include <cuda_fp16.h>
#include <cstdint>

#define D_DIM 512
#define C_DIM 1024
#define M_TILE 64
#define NTHREADS 256

// smem layout (bytes)
#define QOFF   0            // 64 x 512 fp16 raw-q (8 panels SW128); GEMM2 stages 0,1
#define WOFF   65536        // W: 16 panels (64r x 128B) SW128; ALSO GEMM1 even-kc B stages
#define SBOFF  196608       // GEMM1 odd-kc B stage; GEMM2 stage 2 (32KB)
#define REDOFF 229376       // 256 floats
#define INVOFF 230400       // 64 floats
#define SMEM_BYTES 230656
#define ST2SZ  32768

// ---- small device scratch (3 MiB) ----
__device__ __half g_Kh[C_DIM * D_DIM];   // normalized keys fp16
__device__ __half g_Vt[C_DIM * C_DIM];   // val transposed fp16: g_Vt[n*C+k] = val[k*C+n]

// ---- helpers ----
__device__ __forceinline__ uint32_t smem_u32(const void* p) {
    uint32_t a;
    asm("{ .reg .u64 t; cvta.to.shared.u64 t, %1; cvt.u32.u64 %0, t; }" : "=r"(a) : "l"(p));
    return a;
}
#define SWZ(x) ((x) ^ (((x) >> 3) & 0x70))

__device__ __forceinline__ void cp16(uint32_t s, const void* g) {
    asm volatile("cp.async.cg.shared.global [%0], [%1], 16;" :: "r"(s), "l"(g));
}
#define CP_COMMIT() asm volatile("cp.async.commit_group;" ::: "memory")
#define CP_WAIT1()  asm volatile("cp.async.wait_group 1;" ::: "memory")
#define CP_WAIT0()  asm volatile("cp.async.wait_group 0;" ::: "memory")

__device__ __forceinline__ void ldsm4(unsigned r[4], uint32_t a) {
    asm volatile("ldmatrix.sync.aligned.m8n8.x4.shared.b16 {%0,%1,%2,%3}, [%4];"
                 : "=r"(r[0]), "=r"(r[1]), "=r"(r[2]), "=r"(r[3]) : "r"(a));
}
__device__ __forceinline__ void mma16816(float c[4], const unsigned a[4], const unsigned b[2]) {
    asm volatile(
        "mma.sync.aligned.m16n8k16.row.col.f32.f16.f16.f32 "
        "{%0,%1,%2,%3}, {%4,%5,%6,%7}, {%8,%9}, {%0,%1,%2,%3};\n"
        : "+f"(c[0]), "+f"(c[1]), "+f"(c[2]), "+f"(c[3])
        : "r"(a[0]), "r"(a[1]), "r"(a[2]), "r"(a[3]), "r"(b[0]), "r"(b[1]));
}

// sharp(x) = sigmoid(10x-5) + sigmoid(-10x-5)
__device__ __forceinline__ float sharp_fn(float x) {
    const float E = 148.4131591f;      // e^5
    const float E2p1 = 22027.4658f;    // e^10 + 1
    float u = __expf(10.f * x);
    float eu = E * u;
    float num = fmaf(eu, u, fmaf(2.f, u, E));
    float den = fmaf(eu, u, fmaf(E2p1, u, E));
    return __fdividef(num, den);
}

// fill: 256 rows x 64 cols fp16; pg = per-thread global ptr, sdst = dst + thread smem const
template <int LDB>
__device__ __forceinline__ void fillB2p(const __half* __restrict__ pg, uint32_t sdst) {
#pragma unroll
    for (int it = 0; it < 8; ++it)
        cp16(sdst + it * 4096, pg + (size_t)it * 32 * LDB);
}

// ---- merged prep kernel ----
__global__ void prep_kernel(const float* __restrict__ key, const float* __restrict__ val) {
    __shared__ float tile[32][33];
    __shared__ float ws[8];
    __shared__ float sinv;
    const int tid = threadIdx.x;
    if (blockIdx.x < 1024) {
        const int ko = (blockIdx.x & 31) * 32;
        const int no = (blockIdx.x >> 5) * 32;
        const int tx = tid & 31, ty = tid >> 5;
#pragma unroll
        for (int j = 0; j < 32; j += 8)
            tile[ty + j][tx] = val[(size_t)(ko + ty + j) * C_DIM + no + tx];
        __syncthreads();
#pragma unroll
        for (int j = 0; j < 32; j += 8)
            g_Vt[(size_t)(no + ty + j) * C_DIM + ko + tx] = __float2half(tile[tx][ty + j]);
    } else {
        const int r = blockIdx.x - 1024;
        const float* kr = key + (size_t)r * D_DIM;
        float v[2];
        float ss = 0.f;
#pragma unroll
        for (int i = 0; i < 2; ++i) { v[i] = kr[tid + i * 256]; ss += v[i] * v[i]; }
#pragma unroll
        for (int o = 16; o > 0; o >>= 1) ss += __shfl_down_sync(0xffffffffu, ss, o);
        if ((tid & 31) == 0) ws[tid >> 5] = ss;
        __syncthreads();
        if (tid == 0) {
            float s = 0.f;
#pragma unroll
            for (int j = 0; j < 8; ++j) s += ws[j];
            sinv = rsqrtf(s + 1e-12f);
        }
        __syncthreads();
        const float iv = sinv;
#pragma unroll
        for (int i = 0; i < 2; ++i)
            g_Kh[(size_t)r * D_DIM + tid + i * 256] = __float2half(v[i] * iv);
    }
}

// ---- fused main kernel: 256 threads, 8 warps, warp tile 32x64, single-buffered frags ----
__global__ __launch_bounds__(NTHREADS, 1)
void fused_kv_kernel(const float* __restrict__ query, float* __restrict__ out) {
    extern __shared__ char smem[];
    const uint32_t sb = smem_u32(smem);
    float* red = (float*)(smem + REDOFF);
    float* inv = (float*)(smem + INVOFF);

    const int tid  = threadIdx.x;
    const int lane = tid & 31;
    const int wid  = tid >> 5;
    const int wm   = wid >> 2;
    const int wn   = wid & 3;
    const int g    = lane >> 2;
    const int tig  = lane & 3;
    const int lrow = lane & 15;
    const int hs   = lane >> 4;
    const int row0 = blockIdx.x * M_TILE;

    // precomputed LDSM address components:
    // SWZ(row*128 + ks*32 + hs*16) = row*128 + ((ks*32+hs*16) ^ ((lrow&7)*16))
    uint32_t koff[4], arow[2], brow[4];
    {
        const uint32_t xr = (uint32_t)(lrow & 7) * 16u;
#pragma unroll
        for (int ks = 0; ks < 4; ++ks)
            koff[ks] = ((uint32_t)(ks * 32 + hs * 16)) ^ xr;
#pragma unroll
        for (int mi = 0; mi < 2; ++mi)
            arow[mi] = (uint32_t)(wm * 32 + mi * 16 + lrow) * 128u;
#pragma unroll
        for (int pr = 0; pr < 4; ++pr)
            brow[pr] = (uint32_t)(wn * 64 + pr * 16 + lrow) * 128u;
    }
    const uint32_t fr0 = (uint32_t)(tid >> 3);
    const uint32_t fc  = (uint32_t)(tid & 7);
    const uint32_t fs0 = fr0 * 128u + ((fc * 16u) ^ ((fr0 & 7u) * 16u));
    const uint32_t gofs1 = fr0 * D_DIM + fc * 8;
    const uint32_t gofs2 = fr0 * C_DIM + fc * 8;

    // ---- Step 0: load RAW q -> fp16 smem (swizzled) + 1/||q|| ----
    {
        const int r = tid >> 2;
        const int p = tid & 3;
        const float* qrow = query + (size_t)(row0 + r) * D_DIM + p * 128;
        float ss = 0.f;
#pragma unroll
        for (int q = 0; q < 2; ++q) {
            char* pb = smem + QOFF + (2 * p + q) * 8192;
#pragma unroll 4
            for (int j = 0; j < 64; j += 4) {
                float4 v = *(const float4*)(qrow + q * 64 + j);
                ss += v.x * v.x + v.y * v.y + v.z * v.z + v.w * v.w;
                int b = r * 128 + j * 2;
                *(__half2*)(pb + SWZ(b))     = __floats2half2_rn(v.x, v.y);
                *(__half2*)(pb + SWZ(b + 4)) = __floats2half2_rn(v.z, v.w);
            }
        }
        red[tid] = ss;
        __syncthreads();
        if (tid < M_TILE)
            inv[tid] = rsqrtf(red[tid * 4] + red[tid * 4 + 1] +
                              red[tid * 4 + 2] + red[tid * 4 + 3] + 1e-12f);
        __syncthreads();
    }
    float qa[4];
#pragma unroll
    for (int j = 0; j < 4; ++j) qa[j] = inv[wm * 32 + j * 8 + g];
    __syncthreads();
    if (tid < M_TILE) red[tid] = 0.f;

    // ---- GEMM1: W = sharp(qinv * (q @ Kn^T)); 32 iters (4 nc x 8 kc) ----
    {
        float acc[2][8][4];
        float rs[2][2] = {{0.f, 0.f}, {0.f, 0.f}};
        fillB2p<D_DIM>(g_Kh + gofs1, sb + WOFF + fs0);
        CP_COMMIT();

#pragma unroll 1
        for (int t = 0; t < 32; ++t) {
            const int nc = t >> 3, kc = t & 7;
            CP_WAIT0();
            __syncthreads();
            if (t + 1 < 32) {
                const int u = t + 1;
                const uint32_t dst = (u & 1) ? (uint32_t)SBOFF
                                             : (uint32_t)(WOFF + ((u >> 3) << 15));
                fillB2p<D_DIM>(g_Kh + ((size_t)(u >> 3) * 256) * D_DIM + (u & 7) * 64 + gofs1,
                               sb + dst + fs0);
                CP_COMMIT();
            }
            if (kc == 0) {
#pragma unroll
                for (int mi = 0; mi < 2; ++mi)
#pragma unroll
                    for (int ni = 0; ni < 8; ++ni)
#pragma unroll
                        for (int e = 0; e < 4; ++e) acc[mi][ni][e] = 0.f;
            }
            const uint32_t sB = sb + ((t & 1) ? (uint32_t)SBOFF
                                              : (uint32_t)(WOFF + (nc << 15)));
            const uint32_t sA = sb + QOFF + kc * 8192;

#pragma unroll
            for (int ks = 0; ks < 4; ++ks) {
                unsigned a[2][4], b[8][2];
#pragma unroll
                for (int mi = 0; mi < 2; ++mi)
                    ldsm4(a[mi], sA + arow[mi] + koff[ks]);
#pragma unroll
                for (int pr = 0; pr < 4; ++pr) {
                    unsigned r4[4];
                    ldsm4(r4, sB + brow[pr] + koff[ks]);
                    b[pr * 2][0] = r4[0]; b[pr * 2 + 1][0] = r4[1];
                    b[pr * 2][1] = r4[2]; b[pr * 2 + 1][1] = r4[3];
                }
#pragma unroll
                for (int mi = 0; mi < 2; ++mi)
#pragma unroll
                    for (int ni = 0; ni < 8; ++ni)
                        mma16816(acc[mi][ni], a[mi], b[ni]);
            }
            if (kc == 7) {
#pragma unroll
                for (int mi = 0; mi < 2; ++mi) {
#pragma unroll
                    for (int ni = 0; ni < 8; ++ni) {
                        int rr = wm * 32 + mi * 16 + g;
                        int cc = nc * 256 + wn * 64 + ni * 8 + tig * 2;
                        int panel = cc >> 6, c6 = cc & 63;
                        char* base = smem + WOFF + panel * 8192;
                        float w0 = sharp_fn(acc[mi][ni][0] * qa[mi * 2]);
                        float w1 = sharp_fn(acc[mi][ni][1] * qa[mi * 2]);
                        float w2 = sharp_fn(acc[mi][ni][2] * qa[mi * 2 + 1]);
                        float w3 = sharp_fn(acc[mi][ni][3] * qa[mi * 2 + 1]);
                        rs[mi][0] += w0 + w1;
                        rs[mi][1] += w2 + w3;
                        *(__half2*)(base + SWZ(rr * 128 + c6 * 2)) = __floats2half2_rn(w0, w1);
                        *(__half2*)(base + SWZ((rr + 8) * 128 + c6 * 2)) = __floats2half2_rn(w2, w3);
                    }
                }
            }
        }
        atomicAdd(&red[wm * 32 + g],       rs[0][0]);
        atomicAdd(&red[wm * 32 + g + 8],   rs[0][1]);
        atomicAdd(&red[wm * 32 + 16 + g],  rs[1][0]);
        atomicAdd(&red[wm * 32 + 24 + g],  rs[1][1]);
        __syncthreads();
        if (tid < M_TILE) inv[tid] = 1.f / red[tid];
        __syncthreads();
    }

    // ---- GEMM2: out = (1/rowsum) * W @ val; 64 iters (4 nc x 16 kc), 3 rotating stages ----
    {
        float acc[2][8][4];
        uint32_t s0 = QOFF, s1 = QOFF + ST2SZ, s2 = SBOFF;
        fillB2p<C_DIM>(g_Vt + gofs2, sb + s0 + fs0);
        CP_COMMIT();
        fillB2p<C_DIM>(g_Vt + 64 + gofs2, sb + s1 + fs0);
        CP_COMMIT();

#pragma unroll 1
        for (int t = 0; t < 64; ++t) {
            const int nc = t >> 4, kc = t & 15;
            CP_WAIT1();
            __syncthreads();
            {
                const int u = t + 2;
                if (u < 64) {
                    fillB2p<C_DIM>(g_Vt + ((size_t)(u >> 4) * 256) * C_DIM + (u & 15) * 64 + gofs2,
                                   sb + s2 + fs0);
                    CP_COMMIT();
                }
            }
            if (kc == 0) {
#pragma unroll
                for (int mi = 0; mi < 2; ++mi)
#pragma unroll
                    for (int ni = 0; ni < 8; ++ni)
#pragma unroll
                        for (int e = 0; e < 4; ++e) acc[mi][ni][e] = 0.f;
            }
            const uint32_t sB = sb + s0;
            const uint32_t sA = sb + WOFF + kc * 8192;

#pragma unroll
            for (int ks = 0; ks < 4; ++ks) {
                unsigned a[2][4], b[8][2];
#pragma unroll
                for (int mi = 0; mi < 2; ++mi)
                    ldsm4(a[mi], sA + arow[mi] + koff[ks]);
#pragma unroll
                for (int pr = 0; pr < 4; ++pr) {
                    unsigned r4[4];
                    ldsm4(r4, sB + brow[pr] + koff[ks]);
                    b[pr * 2][0] = r4[0]; b[pr * 2 + 1][0] = r4[1];
                    b[pr * 2][1] = r4[2]; b[pr * 2 + 1][1] = r4[3];
                }
#pragma unroll
                for (int mi = 0; mi < 2; ++mi)
#pragma unroll
                    for (int ni = 0; ni < 8; ++ni)
                        mma16816(acc[mi][ni], a[mi], b[ni]);
            }
            if (kc == 15) {
#pragma unroll
                for (int mi = 0; mi < 2; ++mi) {
#pragma unroll
                    for (int ni = 0; ni < 8; ++ni) {
                        int rr = wm * 32 + mi * 16 + g;
                        int cc = nc * 256 + wn * 64 + ni * 8 + tig * 2;
                        float i0 = inv[rr], i8 = inv[rr + 8];
                        *(float2*)(out + (size_t)(row0 + rr) * C_DIM + cc) =
                            make_float2(acc[mi][ni][0] * i0, acc[mi][ni][1] * i0);
                        *(float2*)(out + (size_t)(row0 + rr + 8) * C_DIM + cc) =
                            make_float2(acc[mi][ni][2] * i8, acc[mi][ni][3] * i8);
                    }
                }
            }
            const uint32_t tmp = s0; s0 = s1; s1 = s2; s2 = tmp;
        }
    }
}

// ---------------------------------------------------------------------------
extern "C" void kernel_launch(void* const* d_in, const int* in_sizes, int n_in,
                              void* d_out, int out_size) {
    const float* query = (const float*)d_in[0];
    const float* key   = (const float*)d_in[1];
    const float* val   = (const float*)d_in[2];
    float* out = (float*)d_out;

    const int B = in_sizes[0] / D_DIM;

    prep_kernel<<<2048, 256>>>(key, val);

    cudaFuncSetAttribute(fused_kv_kernel,
                         cudaFuncAttributeMaxDynamicSharedMemorySize, SMEM_BYTES);
    fused_kv_kernel<<<B / M_TILE, NTHREADS, SMEM_BYTES>>>(query, out);
}

// round 14
// speedup vs baseline: 1.0262x; 1.0050x over previous
#include <cuda_runtime.h>
#include <cuda_fp16.h>
#include <cstdint>

#define D_DIM 512
#define C_DIM 1024
#define M_TILE 64
#define NTHREADS 256

// smem layout (bytes)
#define QOFF   0            // 64 x 512 fp16 raw-q (8 panels SW128); GEMM2 stages 0,1
#define WOFF   65536        // W: 16 panels (64r x 128B) SW128; ALSO GEMM1 even-kc B stages
#define SBOFF  196608       // GEMM1 odd-kc B stage; GEMM2 stage 2 (32KB)
#define REDOFF 229376       // 256 floats
#define INVOFF 230400       // 64 floats
#define SMEM_BYTES 230656
#define ST2SZ  32768

// ---- small device scratch (3 MiB) ----
__device__ __half g_Kh[C_DIM * D_DIM];   // normalized keys fp16
__device__ __half g_Vt[C_DIM * C_DIM];   // val transposed fp16: g_Vt[n*C+k] = val[k*C+n]

// ---- helpers ----
__device__ __forceinline__ uint32_t smem_u32(const void* p) {
    uint32_t a;
    asm("{ .reg .u64 t; cvta.to.shared.u64 t, %1; cvt.u32.u64 %0, t; }" : "=r"(a) : "l"(p));
    return a;
}
#define SWZ(x) ((x) ^ (((x) >> 3) & 0x70))

__device__ __forceinline__ void cp16(uint32_t s, const void* g) {
    asm volatile("cp.async.cg.shared.global [%0], [%1], 16;" :: "r"(s), "l"(g));
}
#define CP_COMMIT() asm volatile("cp.async.commit_group;" ::: "memory")
#define CP_WAIT1()  asm volatile("cp.async.wait_group 1;" ::: "memory")
#define CP_WAIT0()  asm volatile("cp.async.wait_group 0;" ::: "memory")

__device__ __forceinline__ void ldsm4(unsigned r[4], uint32_t a) {
    asm volatile("ldmatrix.sync.aligned.m8n8.x4.shared.b16 {%0,%1,%2,%3}, [%4];"
                 : "=r"(r[0]), "=r"(r[1]), "=r"(r[2]), "=r"(r[3]) : "r"(a));
}
__device__ __forceinline__ void mma16816(float c[4], const unsigned a[4], const unsigned b[2]) {
    asm volatile(
        "mma.sync.aligned.m16n8k16.row.col.f32.f16.f16.f32 "
        "{%0,%1,%2,%3}, {%4,%5,%6,%7}, {%8,%9}, {%0,%1,%2,%3};\n"
        : "+f"(c[0]), "+f"(c[1]), "+f"(c[2]), "+f"(c[3])
        : "r"(a[0]), "r"(a[1]), "r"(a[2]), "r"(a[3]), "r"(b[0]), "r"(b[1]));
}

// sharp(x) = sigmoid(10x-5) + sigmoid(-10x-5)
__device__ __forceinline__ float sharp_fn(float x) {
    const float E = 148.4131591f;      // e^5
    const float E2p1 = 22027.4658f;    // e^10 + 1
    float u = __expf(10.f * x);
    float eu = E * u;
    float num = fmaf(eu, u, fmaf(2.f, u, E));
    float den = fmaf(eu, u, fmaf(E2p1, u, E));
    return __fdividef(num, den);
}

// fill: 256 rows x 64 cols fp16; pg = per-thread global ptr, sdst = dst + thread smem const
template <int LDB>
__device__ __forceinline__ void fillB2p(const __half* __restrict__ pg, uint32_t sdst) {
#pragma unroll
    for (int it = 0; it < 8; ++it)
        cp16(sdst + it * 4096, pg + (size_t)it * 32 * LDB);
}

// ---- merged prep kernel ----
__global__ void prep_kernel(const float* __restrict__ key, const float* __restrict__ val) {
    __shared__ float tile[32][33];
    __shared__ float ws[8];
    __shared__ float sinv;
    const int tid = threadIdx.x;
    if (blockIdx.x < 1024) {
        const int ko = (blockIdx.x & 31) * 32;
        const int no = (blockIdx.x >> 5) * 32;
        const int tx = tid & 31, ty = tid >> 5;
#pragma unroll
        for (int j = 0; j < 32; j += 8)
            tile[ty + j][tx] = val[(size_t)(ko + ty + j) * C_DIM + no + tx];
        __syncthreads();
#pragma unroll
        for (int j = 0; j < 32; j += 8)
            g_Vt[(size_t)(no + ty + j) * C_DIM + ko + tx] = __float2half(tile[tx][ty + j]);
    } else {
        const int r = blockIdx.x - 1024;
        const float* kr = key + (size_t)r * D_DIM;
        float v[2];
        float ss = 0.f;
#pragma unroll
        for (int i = 0; i < 2; ++i) { v[i] = kr[tid + i * 256]; ss += v[i] * v[i]; }
#pragma unroll
        for (int o = 16; o > 0; o >>= 1) ss += __shfl_down_sync(0xffffffffu, ss, o);
        if ((tid & 31) == 0) ws[tid >> 5] = ss;
        __syncthreads();
        if (tid == 0) {
            float s = 0.f;
#pragma unroll
            for (int j = 0; j < 8; ++j) s += ws[j];
            sinv = rsqrtf(s + 1e-12f);
        }
        __syncthreads();
        const float iv = sinv;
#pragma unroll
        for (int i = 0; i < 2; ++i)
            g_Kh[(size_t)r * D_DIM + tid + i * 256] = __float2half(v[i] * iv);
    }
}

// ---- fused main kernel: 256 threads, 8 warps, warp tile 32x64 ----
__global__ __launch_bounds__(NTHREADS, 1)
void fused_kv_kernel(const float* __restrict__ query, float* __restrict__ out) {
    extern __shared__ char smem[];
    const uint32_t sb = smem_u32(smem);
    float* red = (float*)(smem + REDOFF);
    float* inv = (float*)(smem + INVOFF);

    const int tid  = threadIdx.x;
    const int lane = tid & 31;
    const int wid  = tid >> 5;
    const int wm   = wid >> 2;
    const int wn   = wid & 3;
    const int g    = lane >> 2;
    const int tig  = lane & 3;
    const int lrow = lane & 15;
    const int hs   = lane >> 4;
    const int row0 = blockIdx.x * M_TILE;

    // precomputed LDSM address components:
    // SWZ(row*128 + ks*32 + hs*16) = row*128 + ((ks*32+hs*16) ^ ((lrow&7)*16))
    uint32_t koff[4], arow[2], brow[4];
    {
        const uint32_t xr = (uint32_t)(lrow & 7) * 16u;
#pragma unroll
        for (int ks = 0; ks < 4; ++ks)
            koff[ks] = ((uint32_t)(ks * 32 + hs * 16)) ^ xr;
#pragma unroll
        for (int mi = 0; mi < 2; ++mi)
            arow[mi] = (uint32_t)(wm * 32 + mi * 16 + lrow) * 128u;
#pragma unroll
        for (int pr = 0; pr < 4; ++pr)
            brow[pr] = (uint32_t)(wn * 64 + pr * 16 + lrow) * 128u;
    }
    const uint32_t fr0 = (uint32_t)(tid >> 3);
    const uint32_t fc  = (uint32_t)(tid & 7);
    const uint32_t fs0 = fr0 * 128u + ((fc * 16u) ^ ((fr0 & 7u) * 16u));
    const uint32_t gofs1 = fr0 * D_DIM + fc * 8;
    const uint32_t gofs2 = fr0 * C_DIM + fc * 8;

    // EARLY: issue GEMM1 stage-0 fill (into W region) so the Q-load phase covers its latency
    fillB2p<D_DIM>(g_Kh + gofs1, sb + WOFF + fs0);
    CP_COMMIT();

    // ---- Step 0: load RAW q -> fp16 smem (swizzled) + 1/||q|| ----
    {
        const int r = tid >> 2;
        const int p = tid & 3;
        const float* qrow = query + (size_t)(row0 + r) * D_DIM + p * 128;
        float ss = 0.f;
#pragma unroll
        for (int q = 0; q < 2; ++q) {
            char* pb = smem + QOFF + (2 * p + q) * 8192;
#pragma unroll 4
            for (int j = 0; j < 64; j += 4) {
                float4 v = *(const float4*)(qrow + q * 64 + j);
                ss += v.x * v.x + v.y * v.y + v.z * v.z + v.w * v.w;
                int b = r * 128 + j * 2;
                *(__half2*)(pb + SWZ(b))     = __floats2half2_rn(v.x, v.y);
                *(__half2*)(pb + SWZ(b + 4)) = __floats2half2_rn(v.z, v.w);
            }
        }
        red[tid] = ss;
        __syncthreads();
        if (tid < M_TILE)
            inv[tid] = rsqrtf(red[tid * 4] + red[tid * 4 + 1] +
                              red[tid * 4 + 2] + red[tid * 4 + 3] + 1e-12f);
        __syncthreads();
    }
    float qa[4];
#pragma unroll
    for (int j = 0; j < 4; ++j) qa[j] = inv[wm * 32 + j * 8 + g];
    __syncthreads();
    if (tid < M_TILE) red[tid] = 0.f;

    // ---- GEMM1: W = sharp(qinv * (q @ Kn^T)); 32 iters (4 nc x 8 kc) ----
    {
        float acc[2][8][4];
        float rs[2][2] = {{0.f, 0.f}, {0.f, 0.f}};

#pragma unroll 1
        for (int t = 0; t < 32; ++t) {
            const int nc = t >> 3, kc = t & 7;
            CP_WAIT0();
            __syncthreads();
            if (t + 1 < 32) {
                const int u = t + 1;
                const uint32_t dst = (u & 1) ? (uint32_t)SBOFF
                                             : (uint32_t)(WOFF + ((u >> 3) << 15));
                fillB2p<D_DIM>(g_Kh + ((size_t)(u >> 3) * 256) * D_DIM + (u & 7) * 64 + gofs1,
                               sb + dst + fs0);
                CP_COMMIT();
            }
            if (kc == 0) {
#pragma unroll
                for (int mi = 0; mi < 2; ++mi)
#pragma unroll
                    for (int ni = 0; ni < 8; ++ni)
#pragma unroll
                        for (int e = 0; e < 4; ++e) acc[mi][ni][e] = 0.f;
            }
            const uint32_t sB = sb + ((t & 1) ? (uint32_t)SBOFF
                                              : (uint32_t)(WOFF + (nc << 15)));
            const uint32_t sA = sb + QOFF + kc * 8192;

#pragma unroll
            for (int ks = 0; ks < 4; ++ks) {
                unsigned a[2][4], b[8][2];
#pragma unroll
                for (int mi = 0; mi < 2; ++mi)
                    ldsm4(a[mi], sA + arow[mi] + koff[ks]);
#pragma unroll
                for (int pr = 0; pr < 4; ++pr) {
                    unsigned r4[4];
                    ldsm4(r4, sB + brow[pr] + koff[ks]);
                    b[pr * 2][0] = r4[0]; b[pr * 2 + 1][0] = r4[1];
                    b[pr * 2][1] = r4[2]; b[pr * 2 + 1][1] = r4[3];
                }
#pragma unroll
                for (int mi = 0; mi < 2; ++mi)
#pragma unroll
                    for (int ni = 0; ni < 8; ++ni)
                        mma16816(acc[mi][ni], a[mi], b[ni]);
            }
            if (kc == 7) {
#pragma unroll
                for (int mi = 0; mi < 2; ++mi) {
#pragma unroll
                    for (int ni = 0; ni < 8; ++ni) {
                        int rr = wm * 32 + mi * 16 + g;
                        int cc = nc * 256 + wn * 64 + ni * 8 + tig * 2;
                        int panel = cc >> 6, c6 = cc & 63;
                        char* base = smem + WOFF + panel * 8192;
                        float w0 = sharp_fn(acc[mi][ni][0] * qa[mi * 2]);
                        float w1 = sharp_fn(acc[mi][ni][1] * qa[mi * 2]);
                        float w2 = sharp_fn(acc[mi][ni][2] * qa[mi * 2 + 1]);
                        float w3 = sharp_fn(acc[mi][ni][3] * qa[mi * 2 + 1]);
                        rs[mi][0] += w0 + w1;
                        rs[mi][1] += w2 + w3;
                        *(__half2*)(base + SWZ(rr * 128 + c6 * 2)) = __floats2half2_rn(w0, w1);
                        *(__half2*)(base + SWZ((rr + 8) * 128 + c6 * 2)) = __floats2half2_rn(w2, w3);
                    }
                }
            }
        }
        // OVERLAP: issue GEMM2 stage-0 fill now (overwrites Q panels 0-3; any straggler
        // warp at t=31 reads only Q panel 7 (kc=7) -> no conflict). Latency hidden under
        // the rowsum reduction below.
        fillB2p<C_DIM>(g_Vt + gofs2, sb + QOFF + fs0);
        CP_COMMIT();

        atomicAdd(&red[wm * 32 + g],       rs[0][0]);
        atomicAdd(&red[wm * 32 + g + 8],   rs[0][1]);
        atomicAdd(&red[wm * 32 + 16 + g],  rs[1][0]);
        atomicAdd(&red[wm * 32 + 24 + g],  rs[1][1]);
        __syncthreads();
        if (tid < M_TILE) inv[tid] = 1.f / red[tid];
        __syncthreads();
    }

    // ---- GEMM2: out = (1/rowsum) * W @ val; 64 iters (4 nc x 16 kc), 3 rotating stages ----
    {
        float acc[2][8][4];
        uint32_t s0 = QOFF, s1 = QOFF + ST2SZ, s2 = SBOFF;
        // s0 already in flight; issue s1 (Q panels 4-7 now dead after the syncs above)
        fillB2p<C_DIM>(g_Vt + 64 + gofs2, sb + s1 + fs0);
        CP_COMMIT();

#pragma unroll 1
        for (int t = 0; t < 64; ++t) {
            const int nc = t >> 4, kc = t & 15;
            CP_WAIT1();
            __syncthreads();
            {
                const int u = t + 2;
                if (u < 64) {
                    fillB2p<C_DIM>(g_Vt + ((size_t)(u >> 4) * 256) * C_DIM + (u & 15) * 64 + gofs2,
                                   sb + s2 + fs0);
                    CP_COMMIT();
                }
            }
            if (kc == 0) {
#pragma unroll
                for (int mi = 0; mi < 2; ++mi)
#pragma unroll
                    for (int ni = 0; ni < 8; ++ni)
#pragma unroll
                        for (int e = 0; e < 4; ++e) acc[mi][ni][e] = 0.f;
            }
            const uint32_t sB = sb + s0;
            const uint32_t sA = sb + WOFF + kc * 8192;

#pragma unroll
            for (int ks = 0; ks < 4; ++ks) {
                unsigned a[2][4], b[8][2];
#pragma unroll
                for (int mi = 0; mi < 2; ++mi)
                    ldsm4(a[mi], sA + arow[mi] + koff[ks]);
#pragma unroll
                for (int pr = 0; pr < 4; ++pr) {
                    unsigned r4[4];
                    ldsm4(r4, sB + brow[pr] + koff[ks]);
                    b[pr * 2][0] = r4[0]; b[pr * 2 + 1][0] = r4[1];
                    b[pr * 2][1] = r4[2]; b[pr * 2 + 1][1] = r4[3];
                }
#pragma unroll
                for (int mi = 0; mi < 2; ++mi)
#pragma unroll
                    for (int ni = 0; ni < 8; ++ni)
                        mma16816(acc[mi][ni], a[mi], b[ni]);
            }
            if (kc == 15) {
#pragma unroll
                for (int mi = 0; mi < 2; ++mi) {
#pragma unroll
                    for (int ni = 0; ni < 8; ++ni) {
                        int rr = wm * 32 + mi * 16 + g;
                        int cc = nc * 256 + wn * 64 + ni * 8 + tig * 2;
                        float i0 = inv[rr], i8 = inv[rr + 8];
                        *(float2*)(out + (size_t)(row0 + rr) * C_DIM + cc) =
                            make_float2(acc[mi][ni][0] * i0, acc[mi][ni][1] * i0);
                        *(float2*)(out + (size_t)(row0 + rr + 8) * C_DIM + cc) =
                            make_float2(acc[mi][ni][2] * i8, acc[mi][ni][3] * i8);
                    }
                }
            }
            const uint32_t tmp = s0; s0 = s1; s1 = s2; s2 = tmp;
        }
    }
}

// ---------------------------------------------------------------------------
extern "C" void kernel_launch(void* const* d_in, const int* in_sizes, int n_in,
                              void* d_out, int out_size) {
    const float* query = (const float*)d_in[0];
    const float* key   = (const float*)d_in[1];
    const float* val   = (const float*)d_in[2];
    float* out = (float*)d_out;

    const int B = in_sizes[0] / D_DIM;

    prep_kernel<<<2048, 256>>>(key, val);

    cudaFuncSetAttribute(fused_kv_kernel,
                         cudaFuncAttributeMaxDynamicSharedMemorySize, SMEM_BYTES);
    fused_kv_kernel<<<B / M_TILE, NTHREADS, SMEM_BYTES>>>(query, out);
}

// round 15
// speedup vs baseline: 1.0431x; 1.0165x over previous
#include <cuda_runtime.h>
#include <cuda_fp16.h>
#include <cstdint>

#define D_DIM 512
#define C_DIM 1024
#define M_TILE 64
#define NTHREADS 256

// smem layout (bytes)
#define QOFF   0            // 64 x 512 fp16 raw-q (8 panels SW128); GEMM2 stages 0,1
#define WOFF   65536        // W: 16 panels (64r x 128B) SW128; ALSO GEMM1 even-kc B stages
#define SBOFF  196608       // GEMM1 odd-kc B stage; GEMM2 stage 2 (32KB)
#define REDOFF 229376       // 256 floats
#define INVOFF 230400       // 64 floats
#define SMEM_BYTES 230656
#define ST2SZ  32768

// ---- small device scratch (3 MiB) ----
__device__ __half g_Kh[C_DIM * D_DIM];   // normalized keys fp16
__device__ __half g_Vt[C_DIM * C_DIM];   // val transposed fp16: g_Vt[n*C+k] = val[k*C+n]

// ---- helpers ----
__device__ __forceinline__ uint32_t smem_u32(const void* p) {
    uint32_t a;
    asm("{ .reg .u64 t; cvta.to.shared.u64 t, %1; cvt.u32.u64 %0, t; }" : "=r"(a) : "l"(p));
    return a;
}
#define SWZ(x) ((x) ^ (((x) >> 3) & 0x70))

__device__ __forceinline__ void cp16(uint32_t s, const void* g) {
    asm volatile("cp.async.cg.shared.global [%0], [%1], 16;" :: "r"(s), "l"(g));
}
#define CP_COMMIT() asm volatile("cp.async.commit_group;" ::: "memory")
#define CP_WAIT1()  asm volatile("cp.async.wait_group 1;" ::: "memory")
#define CP_WAIT0()  asm volatile("cp.async.wait_group 0;" ::: "memory")

__device__ __forceinline__ void ldsm4(unsigned r[4], uint32_t a) {
    asm volatile("ldmatrix.sync.aligned.m8n8.x4.shared.b16 {%0,%1,%2,%3}, [%4];"
                 : "=r"(r[0]), "=r"(r[1]), "=r"(r[2]), "=r"(r[3]) : "r"(a));
}
// fp32-accumulator HMMA
__device__ __forceinline__ void mma16816(float c[4], const unsigned a[4], const unsigned b[2]) {
    asm volatile(
        "mma.sync.aligned.m16n8k16.row.col.f32.f16.f16.f32 "
        "{%0,%1,%2,%3}, {%4,%5,%6,%7}, {%8,%9}, {%0,%1,%2,%3};\n"
        : "+f"(c[0]), "+f"(c[1]), "+f"(c[2]), "+f"(c[3])
        : "r"(a[0]), "r"(a[1]), "r"(a[2]), "r"(a[3]), "r"(b[0]), "r"(b[1]));
}
// fp16-accumulator HMMA (rate experiment): D/C are 2 b32 regs = 4 halves, same element map
__device__ __forceinline__ void mma16816h(unsigned c[2], const unsigned a[4], const unsigned b[2]) {
    asm volatile(
        "mma.sync.aligned.m16n8k16.row.col.f16.f16.f16.f16 "
        "{%0,%1}, {%2,%3,%4,%5}, {%6,%7}, {%0,%1};\n"
        : "+r"(c[0]), "+r"(c[1])
        : "r"(a[0]), "r"(a[1]), "r"(a[2]), "r"(a[3]), "r"(b[0]), "r"(b[1]));
}

// sharp(x) = sigmoid(10x-5) + sigmoid(-10x-5)
__device__ __forceinline__ float sharp_fn(float x) {
    const float E = 148.4131591f;      // e^5
    const float E2p1 = 22027.4658f;    // e^10 + 1
    float u = __expf(10.f * x);
    float eu = E * u;
    float num = fmaf(eu, u, fmaf(2.f, u, E));
    float den = fmaf(eu, u, fmaf(E2p1, u, E));
    return __fdividef(num, den);
}

// fill: 256 rows x 64 cols fp16; pg = per-thread global ptr, sdst = dst + thread smem const
template <int LDB>
__device__ __forceinline__ void fillB2p(const __half* __restrict__ pg, uint32_t sdst) {
#pragma unroll
    for (int it = 0; it < 8; ++it)
        cp16(sdst + it * 4096, pg + (size_t)it * 32 * LDB);
}

// ---- merged prep kernel ----
__global__ void prep_kernel(const float* __restrict__ key, const float* __restrict__ val) {
    __shared__ float tile[32][33];
    __shared__ float ws[8];
    __shared__ float sinv;
    const int tid = threadIdx.x;
    if (blockIdx.x < 1024) {
        const int ko = (blockIdx.x & 31) * 32;
        const int no = (blockIdx.x >> 5) * 32;
        const int tx = tid & 31, ty = tid >> 5;
#pragma unroll
        for (int j = 0; j < 32; j += 8)
            tile[ty + j][tx] = val[(size_t)(ko + ty + j) * C_DIM + no + tx];
        __syncthreads();
#pragma unroll
        for (int j = 0; j < 32; j += 8)
            g_Vt[(size_t)(no + ty + j) * C_DIM + ko + tx] = __float2half(tile[tx][ty + j]);
    } else {
        const int r = blockIdx.x - 1024;
        const float* kr = key + (size_t)r * D_DIM;
        float v[2];
        float ss = 0.f;
#pragma unroll
        for (int i = 0; i < 2; ++i) { v[i] = kr[tid + i * 256]; ss += v[i] * v[i]; }
#pragma unroll
        for (int o = 16; o > 0; o >>= 1) ss += __shfl_down_sync(0xffffffffu, ss, o);
        if ((tid & 31) == 0) ws[tid >> 5] = ss;
        __syncthreads();
        if (tid == 0) {
            float s = 0.f;
#pragma unroll
            for (int j = 0; j < 8; ++j) s += ws[j];
            sinv = rsqrtf(s + 1e-12f);
        }
        __syncthreads();
        const float iv = sinv;
#pragma unroll
        for (int i = 0; i < 2; ++i)
            g_Kh[(size_t)r * D_DIM + tid + i * 256] = __float2half(v[i] * iv);
    }
}

// ---- fused main kernel: 256 threads, 8 warps, warp tile 32x64 ----
__global__ __launch_bounds__(NTHREADS, 1)
void fused_kv_kernel(const float* __restrict__ query, float* __restrict__ out) {
    extern __shared__ char smem[];
    const uint32_t sb = smem_u32(smem);
    float* red = (float*)(smem + REDOFF);
    float* inv = (float*)(smem + INVOFF);

    const int tid  = threadIdx.x;
    const int lane = tid & 31;
    const int wid  = tid >> 5;
    const int wm   = wid >> 2;
    const int wn   = wid & 3;
    const int g    = lane >> 2;
    const int tig  = lane & 3;
    const int lrow = lane & 15;
    const int hs   = lane >> 4;
    const int row0 = blockIdx.x * M_TILE;

    // precomputed LDSM address components
    uint32_t koff[4], arow[2], brow[4];
    {
        const uint32_t xr = (uint32_t)(lrow & 7) * 16u;
#pragma unroll
        for (int ks = 0; ks < 4; ++ks)
            koff[ks] = ((uint32_t)(ks * 32 + hs * 16)) ^ xr;
#pragma unroll
        for (int mi = 0; mi < 2; ++mi)
            arow[mi] = (uint32_t)(wm * 32 + mi * 16 + lrow) * 128u;
#pragma unroll
        for (int pr = 0; pr < 4; ++pr)
            brow[pr] = (uint32_t)(wn * 64 + pr * 16 + lrow) * 128u;
    }
    const uint32_t fr0 = (uint32_t)(tid >> 3);
    const uint32_t fc  = (uint32_t)(tid & 7);
    const uint32_t fs0 = fr0 * 128u + ((fc * 16u) ^ ((fr0 & 7u) * 16u));
    const uint32_t gofs1 = fr0 * D_DIM + fc * 8;
    const uint32_t gofs2 = fr0 * C_DIM + fc * 8;

    // EARLY: GEMM1 stage-0 fill (latency covered by Q-load phase)
    fillB2p<D_DIM>(g_Kh + gofs1, sb + WOFF + fs0);
    CP_COMMIT();

    // ---- Step 0: load RAW q -> fp16 smem (swizzled) + 1/||q|| ----
    {
        const int r = tid >> 2;
        const int p = tid & 3;
        const float* qrow = query + (size_t)(row0 + r) * D_DIM + p * 128;
        float ss = 0.f;
#pragma unroll
        for (int q = 0; q < 2; ++q) {
            char* pb = smem + QOFF + (2 * p + q) * 8192;
#pragma unroll 4
            for (int j = 0; j < 64; j += 4) {
                float4 v = *(const float4*)(qrow + q * 64 + j);
                ss += v.x * v.x + v.y * v.y + v.z * v.z + v.w * v.w;
                int b = r * 128 + j * 2;
                *(__half2*)(pb + SWZ(b))     = __floats2half2_rn(v.x, v.y);
                *(__half2*)(pb + SWZ(b + 4)) = __floats2half2_rn(v.z, v.w);
            }
        }
        red[tid] = ss;
        __syncthreads();
        if (tid < M_TILE)
            inv[tid] = rsqrtf(red[tid * 4] + red[tid * 4 + 1] +
                              red[tid * 4 + 2] + red[tid * 4 + 3] + 1e-12f);
        __syncthreads();
    }
    float qa[4];
#pragma unroll
    for (int j = 0; j < 4; ++j) qa[j] = inv[wm * 32 + j * 8 + g];
    __syncthreads();
    if (tid < M_TILE) red[tid] = 0.f;

    // ---- GEMM1: W = sharp(qinv * (q @ Kn^T)); fp16 accumulators (rate experiment) ----
    {
        unsigned acch[2][8][2];
        float rs[2][2] = {{0.f, 0.f}, {0.f, 0.f}};

#pragma unroll 1
        for (int t = 0; t < 32; ++t) {
            const int nc = t >> 3, kc = t & 7;
            CP_WAIT0();
            __syncthreads();
            if (t + 1 < 32) {
                const int u = t + 1;
                const uint32_t dst = (u & 1) ? (uint32_t)SBOFF
                                             : (uint32_t)(WOFF + ((u >> 3) << 15));
                fillB2p<D_DIM>(g_Kh + ((size_t)(u >> 3) * 256) * D_DIM + (u & 7) * 64 + gofs1,
                               sb + dst + fs0);
                CP_COMMIT();
            }
            if (kc == 0) {
#pragma unroll
                for (int mi = 0; mi < 2; ++mi)
#pragma unroll
                    for (int ni = 0; ni < 8; ++ni) {
                        acch[mi][ni][0] = 0u;
                        acch[mi][ni][1] = 0u;
                    }
            }
            const uint32_t sB = sb + ((t & 1) ? (uint32_t)SBOFF
                                              : (uint32_t)(WOFF + (nc << 15)));
            const uint32_t sA = sb + QOFF + kc * 8192;

#pragma unroll
            for (int ks = 0; ks < 4; ++ks) {
                unsigned a[2][4], b[8][2];
#pragma unroll
                for (int mi = 0; mi < 2; ++mi)
                    ldsm4(a[mi], sA + arow[mi] + koff[ks]);
#pragma unroll
                for (int pr = 0; pr < 4; ++pr) {
                    unsigned r4[4];
                    ldsm4(r4, sB + brow[pr] + koff[ks]);
                    b[pr * 2][0] = r4[0]; b[pr * 2 + 1][0] = r4[1];
                    b[pr * 2][1] = r4[2]; b[pr * 2 + 1][1] = r4[3];
                }
#pragma unroll
                for (int mi = 0; mi < 2; ++mi)
#pragma unroll
                    for (int ni = 0; ni < 8; ++ni)
                        mma16816h(acch[mi][ni], a[mi], b[ni]);
            }
            if (kc == 7) {
#pragma unroll
                for (int mi = 0; mi < 2; ++mi) {
#pragma unroll
                    for (int ni = 0; ni < 8; ++ni) {
                        int rr = wm * 32 + mi * 16 + g;
                        int cc = nc * 256 + wn * 64 + ni * 8 + tig * 2;
                        int panel = cc >> 6, c6 = cc & 63;
                        char* base = smem + WOFF + panel * 8192;
                        float2 f0 = __half22float2(*(__half2*)&acch[mi][ni][0]);
                        float2 f1 = __half22float2(*(__half2*)&acch[mi][ni][1]);
                        float w0 = sharp_fn(f0.x * qa[mi * 2]);
                        float w1 = sharp_fn(f0.y * qa[mi * 2]);
                        float w2 = sharp_fn(f1.x * qa[mi * 2 + 1]);
                        float w3 = sharp_fn(f1.y * qa[mi * 2 + 1]);
                        rs[mi][0] += w0 + w1;
                        rs[mi][1] += w2 + w3;
                        *(__half2*)(base + SWZ(rr * 128 + c6 * 2)) = __floats2half2_rn(w0, w1);
                        *(__half2*)(base + SWZ((rr + 8) * 128 + c6 * 2)) = __floats2half2_rn(w2, w3);
                    }
                }
            }
        }
        // OVERLAP: GEMM2 stage-0 fill (overwrites Q panels 0-3; stragglers read only panel 7)
        fillB2p<C_DIM>(g_Vt + gofs2, sb + QOFF + fs0);
        CP_COMMIT();

        atomicAdd(&red[wm * 32 + g],       rs[0][0]);
        atomicAdd(&red[wm * 32 + g + 8],   rs[0][1]);
        atomicAdd(&red[wm * 32 + 16 + g],  rs[1][0]);
        atomicAdd(&red[wm * 32 + 24 + g],  rs[1][1]);
        __syncthreads();
        if (tid < M_TILE) inv[tid] = 1.f / red[tid];
        __syncthreads();
    }

    // ---- GEMM2: out = (1/rowsum) * W @ val; fp32 accumulators (precision-critical) ----
    {
        float acc[2][8][4];
        uint32_t s0 = QOFF, s1 = QOFF + ST2SZ, s2 = SBOFF;
        fillB2p<C_DIM>(g_Vt + 64 + gofs2, sb + s1 + fs0);
        CP_COMMIT();

#pragma unroll 1
        for (int t = 0; t < 64; ++t) {
            const int nc = t >> 4, kc = t & 15;
            CP_WAIT1();
            __syncthreads();
            {
                const int u = t + 2;
                if (u < 64) {
                    fillB2p<C_DIM>(g_Vt + ((size_t)(u >> 4) * 256) * C_DIM + (u & 15) * 64 + gofs2,
                                   sb + s2 + fs0);
                    CP_COMMIT();
                }
            }
            if (kc == 0) {
#pragma unroll
                for (int mi = 0; mi < 2; ++mi)
#pragma unroll
                    for (int ni = 0; ni < 8; ++ni)
#pragma unroll
                        for (int e = 0; e < 4; ++e) acc[mi][ni][e] = 0.f;
            }
            const uint32_t sB = sb + s0;
            const uint32_t sA = sb + WOFF + kc * 8192;

#pragma unroll
            for (int ks = 0; ks < 4; ++ks) {
                unsigned a[2][4], b[8][2];
#pragma unroll
                for (int mi = 0; mi < 2; ++mi)
                    ldsm4(a[mi], sA + arow[mi] + koff[ks]);
#pragma unroll
                for (int pr = 0; pr < 4; ++pr) {
                    unsigned r4[4];
                    ldsm4(r4, sB + brow[pr] + koff[ks]);
                    b[pr * 2][0] = r4[0]; b[pr * 2 + 1][0] = r4[1];
                    b[pr * 2][1] = r4[2]; b[pr * 2 + 1][1] = r4[3];
                }
#pragma unroll
                for (int mi = 0; mi < 2; ++mi)
#pragma unroll
                    for (int ni = 0; ni < 8; ++ni)
                        mma16816(acc[mi][ni], a[mi], b[ni]);
            }
            if (kc == 15) {
#pragma unroll
                for (int mi = 0; mi < 2; ++mi) {
#pragma unroll
                    for (int ni = 0; ni < 8; ++ni) {
                        int rr = wm * 32 + mi * 16 + g;
                        int cc = nc * 256 + wn * 64 + ni * 8 + tig * 2;
                        float i0 = inv[rr], i8 = inv[rr + 8];
                        *(float2*)(out + (size_t)(row0 + rr) * C_DIM + cc) =
                            make_float2(acc[mi][ni][0] * i0, acc[mi][ni][1] * i0);
                        *(float2*)(out + (size_t)(row0 + rr + 8) * C_DIM + cc) =
                            make_float2(acc[mi][ni][2] * i8, acc[mi][ni][3] * i8);
                    }
                }
            }
            const uint32_t tmp = s0; s0 = s1; s1 = s2; s2 = tmp;
        }
    }
}

// ---------------------------------------------------------------------------
extern "C" void kernel_launch(void* const* d_in, const int* in_sizes, int n_in,
                              void* d_out, int out_size) {
    const float* query = (const float*)d_in[0];
    const float* key   = (const float*)d_in[1];
    const float* val   = (const float*)d_in[2];
    float* out = (float*)d_out;

    const int B = in_sizes[0] / D_DIM;

    prep_kernel<<<2048, 256>>>(key, val);

    cudaFuncSetAttribute(fused_kv_kernel,
                         cudaFuncAttributeMaxDynamicSharedMemorySize, SMEM_BYTES);
    fused_kv_kernel<<<B / M_TILE, NTHREADS, SMEM_BYTES>>>(query, out);
}

// round 16
// speedup vs baseline: 1.0539x; 1.0104x over previous
#include <cuda_runtime.h>
#include <cuda_fp16.h>
#include <cstdint>

#define D_DIM 512
#define C_DIM 1024
#define M_TILE 64
#define NTHREADS 256

// smem layout (bytes)
#define QOFF   0            // 64 x 512 fp16 raw-q (8 panels SW128); GEMM2 stages 0,1
#define WOFF   65536        // W: 16 panels (64r x 128B) SW128; ALSO GEMM1 even-kc B stages
#define SBOFF  196608       // GEMM1 odd-kc B stage; GEMM2 stage 2 (32KB)
#define REDOFF 229376       // 256 floats
#define INVOFF 230400       // 64 floats
#define SMEM_BYTES 230656
#define ST2SZ  32768

// ---- small device scratch (3 MiB) ----
__device__ __half g_Kh[C_DIM * D_DIM];   // normalized keys fp16
__device__ __half g_Vt[C_DIM * C_DIM];   // val transposed fp16: g_Vt[n*C+k] = val[k*C+n]

// ---- helpers ----
__device__ __forceinline__ uint32_t smem_u32(const void* p) {
    uint32_t a;
    asm("{ .reg .u64 t; cvta.to.shared.u64 t, %1; cvt.u32.u64 %0, t; }" : "=r"(a) : "l"(p));
    return a;
}
#define SWZ(x) ((x) ^ (((x) >> 3) & 0x70))

__device__ __forceinline__ void cp16(uint32_t s, const void* g) {
    asm volatile("cp.async.cg.shared.global [%0], [%1], 16;" :: "r"(s), "l"(g));
}
#define CP_COMMIT() asm volatile("cp.async.commit_group;" ::: "memory")
#define CP_WAIT1()  asm volatile("cp.async.wait_group 1;" ::: "memory")
#define CP_WAIT0()  asm volatile("cp.async.wait_group 0;" ::: "memory")

__device__ __forceinline__ void ldsm4(unsigned r[4], uint32_t a) {
    asm volatile("ldmatrix.sync.aligned.m8n8.x4.shared.b16 {%0,%1,%2,%3}, [%4];"
                 : "=r"(r[0]), "=r"(r[1]), "=r"(r[2]), "=r"(r[3]) : "r"(a));
}
// fp32-accumulator HMMA
__device__ __forceinline__ void mma16816(float c[4], const unsigned a[4], const unsigned b[2]) {
    asm volatile(
        "mma.sync.aligned.m16n8k16.row.col.f32.f16.f16.f32 "
        "{%0,%1,%2,%3}, {%4,%5,%6,%7}, {%8,%9}, {%0,%1,%2,%3};\n"
        : "+f"(c[0]), "+f"(c[1]), "+f"(c[2]), "+f"(c[3])
        : "r"(a[0]), "r"(a[1]), "r"(a[2]), "r"(a[3]), "r"(b[0]), "r"(b[1]));
}
// fp16-accumulator HMMA (GEMM1; same issue rate, halves acc registers)
__device__ __forceinline__ void mma16816h(unsigned c[2], const unsigned a[4], const unsigned b[2]) {
    asm volatile(
        "mma.sync.aligned.m16n8k16.row.col.f16.f16.f16.f16 "
        "{%0,%1}, {%2,%3,%4,%5}, {%6,%7}, {%0,%1};\n"
        : "+r"(c[0]), "+r"(c[1])
        : "r"(a[0]), "r"(a[1]), "r"(a[2]), "r"(a[3]), "r"(b[0]), "r"(b[1]));
}

// sharp(x) = sigmoid(10x-5) + sigmoid(-10x-5)
__device__ __forceinline__ float sharp_fn(float x) {
    const float E = 148.4131591f;      // e^5
    const float E2p1 = 22027.4658f;    // e^10 + 1
    float u = __expf(10.f * x);
    float eu = E * u;
    float num = fmaf(eu, u, fmaf(2.f, u, E));
    float den = fmaf(eu, u, fmaf(E2p1, u, E));
    return __fdividef(num, den);
}

// fill: 256 rows x 64 cols fp16; pg = per-thread global ptr, sdst = dst + thread smem const
template <int LDB>
__device__ __forceinline__ void fillB2p(const __half* __restrict__ pg, uint32_t sdst) {
#pragma unroll
    for (int it = 0; it < 8; ++it)
        cp16(sdst + it * 4096, pg + (size_t)it * 32 * LDB);
}

// ---- merged prep kernel ----
__global__ void prep_kernel(const float* __restrict__ key, const float* __restrict__ val) {
    __shared__ float tile[32][33];
    __shared__ float ws[8];
    __shared__ float sinv;
    const int tid = threadIdx.x;
    if (blockIdx.x < 1024) {
        const int ko = (blockIdx.x & 31) * 32;
        const int no = (blockIdx.x >> 5) * 32;
        const int tx = tid & 31, ty = tid >> 5;
#pragma unroll
        for (int j = 0; j < 32; j += 8)
            tile[ty + j][tx] = val[(size_t)(ko + ty + j) * C_DIM + no + tx];
        __syncthreads();
#pragma unroll
        for (int j = 0; j < 32; j += 8)
            g_Vt[(size_t)(no + ty + j) * C_DIM + ko + tx] = __float2half(tile[tx][ty + j]);
    } else {
        const int r = blockIdx.x - 1024;
        const float* kr = key + (size_t)r * D_DIM;
        float v[2];
        float ss = 0.f;
#pragma unroll
        for (int i = 0; i < 2; ++i) { v[i] = kr[tid + i * 256]; ss += v[i] * v[i]; }
#pragma unroll
        for (int o = 16; o > 0; o >>= 1) ss += __shfl_down_sync(0xffffffffu, ss, o);
        if ((tid & 31) == 0) ws[tid >> 5] = ss;
        __syncthreads();
        if (tid == 0) {
            float s = 0.f;
#pragma unroll
            for (int j = 0; j < 8; ++j) s += ws[j];
            sinv = rsqrtf(s + 1e-12f);
        }
        __syncthreads();
        const float iv = sinv;
#pragma unroll
        for (int i = 0; i < 2; ++i)
            g_Kh[(size_t)r * D_DIM + tid + i * 256] = __float2half(v[i] * iv);
    }
}

// ---- fused main kernel: 256 threads, 8 warps, warp tile 32x64 ----
__global__ __launch_bounds__(NTHREADS, 1)
void fused_kv_kernel(const float* __restrict__ query, float* __restrict__ out) {
    extern __shared__ char smem[];
    const uint32_t sb = smem_u32(smem);
    float* red = (float*)(smem + REDOFF);
    float* inv = (float*)(smem + INVOFF);

    const int tid  = threadIdx.x;
    const int lane = tid & 31;
    const int wid  = tid >> 5;
    const int wm   = wid >> 2;
    const int wn   = wid & 3;
    const int g    = lane >> 2;
    const int tig  = lane & 3;
    const int lrow = lane & 15;
    const int hs   = lane >> 4;
    const int row0 = blockIdx.x * M_TILE;

    // precomputed LDSM address components
    uint32_t koff[4], arow[2], brow[4];
    {
        const uint32_t xr = (uint32_t)(lrow & 7) * 16u;
#pragma unroll
        for (int ks = 0; ks < 4; ++ks)
            koff[ks] = ((uint32_t)(ks * 32 + hs * 16)) ^ xr;
#pragma unroll
        for (int mi = 0; mi < 2; ++mi)
            arow[mi] = (uint32_t)(wm * 32 + mi * 16 + lrow) * 128u;
#pragma unroll
        for (int pr = 0; pr < 4; ++pr)
            brow[pr] = (uint32_t)(wn * 64 + pr * 16 + lrow) * 128u;
    }
    const uint32_t fr0 = (uint32_t)(tid >> 3);
    const uint32_t fc  = (uint32_t)(tid & 7);
    const uint32_t fs0 = fr0 * 128u + ((fc * 16u) ^ ((fr0 & 7u) * 16u));
    const uint32_t gofs1 = fr0 * D_DIM + fc * 8;
    const uint32_t gofs2 = fr0 * C_DIM + fc * 8;

    // EARLY: GEMM1 stage-0 fill (latency covered by Q-load phase)
    fillB2p<D_DIM>(g_Kh + gofs1, sb + WOFF + fs0);
    CP_COMMIT();

    // ---- Step 0: load RAW q -> fp16 smem (swizzled) + 1/||q|| ----
    {
        const int r = tid >> 2;
        const int p = tid & 3;
        const float* qrow = query + (size_t)(row0 + r) * D_DIM + p * 128;
        float ss = 0.f;
#pragma unroll
        for (int q = 0; q < 2; ++q) {
            char* pb = smem + QOFF + (2 * p + q) * 8192;
#pragma unroll 4
            for (int j = 0; j < 64; j += 4) {
                float4 v = *(const float4*)(qrow + q * 64 + j);
                ss += v.x * v.x + v.y * v.y + v.z * v.z + v.w * v.w;
                int b = r * 128 + j * 2;
                *(__half2*)(pb + SWZ(b))     = __floats2half2_rn(v.x, v.y);
                *(__half2*)(pb + SWZ(b + 4)) = __floats2half2_rn(v.z, v.w);
            }
        }
        red[tid] = ss;
        __syncthreads();
        if (tid < M_TILE)
            inv[tid] = rsqrtf(red[tid * 4] + red[tid * 4 + 1] +
                              red[tid * 4 + 2] + red[tid * 4 + 3] + 1e-12f);
        __syncthreads();
    }
    float qa[4];
#pragma unroll
    for (int j = 0; j < 4; ++j) qa[j] = inv[wm * 32 + j * 8 + g];
    __syncthreads();
    if (tid < M_TILE) red[tid] = 0.f;

    // ---- GEMM1: W = sharp(qinv * (q @ Kn^T)); fp16 acc, A-frag ks-prefetch ----
    {
        unsigned acch[2][8][2];
        float rs[2][2] = {{0.f, 0.f}, {0.f, 0.f}};

#pragma unroll 1
        for (int t = 0; t < 32; ++t) {
            const int nc = t >> 3, kc = t & 7;
            CP_WAIT0();
            __syncthreads();
            if (t + 1 < 32) {
                const int u = t + 1;
                const uint32_t dst = (u & 1) ? (uint32_t)SBOFF
                                             : (uint32_t)(WOFF + ((u >> 3) << 15));
                fillB2p<D_DIM>(g_Kh + ((size_t)(u >> 3) * 256) * D_DIM + (u & 7) * 64 + gofs1,
                               sb + dst + fs0);
                CP_COMMIT();
            }
            if (kc == 0) {
#pragma unroll
                for (int mi = 0; mi < 2; ++mi)
#pragma unroll
                    for (int ni = 0; ni < 8; ++ni) {
                        acch[mi][ni][0] = 0u;
                        acch[mi][ni][1] = 0u;
                    }
            }
            const uint32_t sB = sb + ((t & 1) ? (uint32_t)SBOFF
                                              : (uint32_t)(WOFF + (nc << 15)));
            const uint32_t sA = sb + QOFF + kc * 8192;

            // A-frag double-buffer across ks; B single-buffered
            unsigned af[2][2][4];
#pragma unroll
            for (int mi = 0; mi < 2; ++mi)
                ldsm4(af[0][mi], sA + arow[mi] + koff[0]);
#pragma unroll
            for (int ks = 0; ks < 4; ++ks) {
                const int cur = ks & 1;
                if (ks < 3)
#pragma unroll
                    for (int mi = 0; mi < 2; ++mi)
                        ldsm4(af[cur ^ 1][mi], sA + arow[mi] + koff[ks + 1]);
                unsigned b[8][2];
#pragma unroll
                for (int pr = 0; pr < 4; ++pr) {
                    unsigned r4[4];
                    ldsm4(r4, sB + brow[pr] + koff[ks]);
                    b[pr * 2][0] = r4[0]; b[pr * 2 + 1][0] = r4[1];
                    b[pr * 2][1] = r4[2]; b[pr * 2 + 1][1] = r4[3];
                }
#pragma unroll
                for (int mi = 0; mi < 2; ++mi)
#pragma unroll
                    for (int ni = 0; ni < 8; ++ni)
                        mma16816h(acch[mi][ni], af[cur][mi], b[ni]);
            }
            if (kc == 7) {
#pragma unroll
                for (int mi = 0; mi < 2; ++mi) {
#pragma unroll
                    for (int ni = 0; ni < 8; ++ni) {
                        int rr = wm * 32 + mi * 16 + g;
                        int cc = nc * 256 + wn * 64 + ni * 8 + tig * 2;
                        int panel = cc >> 6, c6 = cc & 63;
                        char* base = smem + WOFF + panel * 8192;
                        float2 f0 = __half22float2(*(__half2*)&acch[mi][ni][0]);
                        float2 f1 = __half22float2(*(__half2*)&acch[mi][ni][1]);
                        float w0 = sharp_fn(f0.x * qa[mi * 2]);
                        float w1 = sharp_fn(f0.y * qa[mi * 2]);
                        float w2 = sharp_fn(f1.x * qa[mi * 2 + 1]);
                        float w3 = sharp_fn(f1.y * qa[mi * 2 + 1]);
                        rs[mi][0] += w0 + w1;
                        rs[mi][1] += w2 + w3;
                        *(__half2*)(base + SWZ(rr * 128 + c6 * 2)) = __floats2half2_rn(w0, w1);
                        *(__half2*)(base + SWZ((rr + 8) * 128 + c6 * 2)) = __floats2half2_rn(w2, w3);
                    }
                }
            }
        }
        // OVERLAP: GEMM2 stage-0 fill (overwrites Q panels 0-3; stragglers read only panel 7)
        fillB2p<C_DIM>(g_Vt + gofs2, sb + QOFF + fs0);
        CP_COMMIT();

        atomicAdd(&red[wm * 32 + g],       rs[0][0]);
        atomicAdd(&red[wm * 32 + g + 8],   rs[0][1]);
        atomicAdd(&red[wm * 32 + 16 + g],  rs[1][0]);
        atomicAdd(&red[wm * 32 + 24 + g],  rs[1][1]);
        __syncthreads();
        if (tid < M_TILE) inv[tid] = 1.f / red[tid];
        __syncthreads();
    }

    // ---- GEMM2: out = (1/rowsum) * W @ val; fp32 acc, A-frag ks-prefetch ----
    {
        float acc[2][8][4];
        uint32_t s0 = QOFF, s1 = QOFF + ST2SZ, s2 = SBOFF;
        fillB2p<C_DIM>(g_Vt + 64 + gofs2, sb + s1 + fs0);
        CP_COMMIT();

#pragma unroll 1
        for (int t = 0; t < 64; ++t) {
            const int nc = t >> 4, kc = t & 15;
            CP_WAIT1();
            __syncthreads();
            {
                const int u = t + 2;
                if (u < 64) {
                    fillB2p<C_DIM>(g_Vt + ((size_t)(u >> 4) * 256) * C_DIM + (u & 15) * 64 + gofs2,
                                   sb + s2 + fs0);
                    CP_COMMIT();
                }
            }
            if (kc == 0) {
#pragma unroll
                for (int mi = 0; mi < 2; ++mi)
#pragma unroll
                    for (int ni = 0; ni < 8; ++ni)
#pragma unroll
                        for (int e = 0; e < 4; ++e) acc[mi][ni][e] = 0.f;
            }
            const uint32_t sB = sb + s0;
            const uint32_t sA = sb + WOFF + kc * 8192;

            unsigned af[2][2][4];
#pragma unroll
            for (int mi = 0; mi < 2; ++mi)
                ldsm4(af[0][mi], sA + arow[mi] + koff[0]);
#pragma unroll
            for (int ks = 0; ks < 4; ++ks) {
                const int cur = ks & 1;
                if (ks < 3)
#pragma unroll
                    for (int mi = 0; mi < 2; ++mi)
                        ldsm4(af[cur ^ 1][mi], sA + arow[mi] + koff[ks + 1]);
                unsigned b[8][2];
#pragma unroll
                for (int pr = 0; pr < 4; ++pr) {
                    unsigned r4[4];
                    ldsm4(r4, sB + brow[pr] + koff[ks]);
                    b[pr * 2][0] = r4[0]; b[pr * 2 + 1][0] = r4[1];
                    b[pr * 2][1] = r4[2]; b[pr * 2 + 1][1] = r4[3];
                }
#pragma unroll
                for (int mi = 0; mi < 2; ++mi)
#pragma unroll
                    for (int ni = 0; ni < 8; ++ni)
                        mma16816(acc[mi][ni], af[cur][mi], b[ni]);
            }
            if (kc == 15) {
#pragma unroll
                for (int mi = 0; mi < 2; ++mi) {
#pragma unroll
                    for (int ni = 0; ni < 8; ++ni) {
                        int rr = wm * 32 + mi * 16 + g;
                        int cc = nc * 256 + wn * 64 + ni * 8 + tig * 2;
                        float i0 = inv[rr], i8 = inv[rr + 8];
                        *(float2*)(out + (size_t)(row0 + rr) * C_DIM + cc) =
                            make_float2(acc[mi][ni][0] * i0, acc[mi][ni][1] * i0);
                        *(float2*)(out + (size_t)(row0 + rr + 8) * C_DIM + cc) =
                            make_float2(acc[mi][ni][2] * i8, acc[mi][ni][3] * i8);
                    }
                }
            }
            const uint32_t tmp = s0; s0 = s1; s1 = s2; s2 = tmp;
        }
    }
}

// ---------------------------------------------------------------------------
extern "C" void kernel_launch(void* const* d_in, const int* in_sizes, int n_in,
                              void* d_out, int out_size) {
    const float* query = (const float*)d_in[0];
    const float* key   = (const float*)d_in[1];
    const float* val   = (const float*)d_in[2];
    float* out = (float*)d_out;

    const int B = in_sizes[0] / D_DIM;

    prep_kernel<<<2048, 256>>>(key, val);

    cudaFuncSetAttribute(fused_kv_kernel,
                         cudaFuncAttributeMaxDynamicSharedMemorySize, SMEM_BYTES);
    fused_kv_kernel<<<B / M_TILE, NTHREADS, SMEM_BYTES>>>(query, out);
}

// round 17
// speedup vs baseline: 1.0739x; 1.0189x over previous
#include <cuda_runtime.h>
#include <cuda_fp16.h>
#include <cstdint>

#define D_DIM 512
#define C_DIM 1024
#define M_TILE 64
#define NTHREADS 256

// smem layout (bytes)
#define QOFF   0            // 64 x 512 fp16 raw-q (8 panels SW128); GEMM2 stages 0,1
#define WOFF   65536        // W: 16 panels (64r x 128B) SW128; ALSO GEMM1 even-kc B stages
#define SBOFF  196608       // GEMM1 odd-kc B stage; GEMM2 stage 2 (32KB)
#define REDOFF 229376       // 256 floats
#define INVOFF 230400       // 64 floats
#define SMEM_BYTES 230656
#define ST2SZ  32768

// ---- small device scratch (3 MiB) ----
__device__ __half g_Kh[C_DIM * D_DIM];   // normalized keys fp16
__device__ __half g_Vt[C_DIM * C_DIM];   // val transposed fp16: g_Vt[n*C+k] = val[k*C+n]

// ---- helpers ----
__device__ __forceinline__ uint32_t smem_u32(const void* p) {
    uint32_t a;
    asm("{ .reg .u64 t; cvta.to.shared.u64 t, %1; cvt.u32.u64 %0, t; }" : "=r"(a) : "l"(p));
    return a;
}
#define SWZ(x) ((x) ^ (((x) >> 3) & 0x70))

__device__ __forceinline__ void cp16(uint32_t s, const void* g) {
    asm volatile("cp.async.cg.shared.global [%0], [%1], 16;" :: "r"(s), "l"(g));
}
#define CP_COMMIT() asm volatile("cp.async.commit_group;" ::: "memory")
#define CP_WAIT1()  asm volatile("cp.async.wait_group 1;" ::: "memory")
#define CP_WAIT0()  asm volatile("cp.async.wait_group 0;" ::: "memory")

__device__ __forceinline__ void ldsm4(unsigned r[4], uint32_t a) {
    asm volatile("ldmatrix.sync.aligned.m8n8.x4.shared.b16 {%0,%1,%2,%3}, [%4];"
                 : "=r"(r[0]), "=r"(r[1]), "=r"(r[2]), "=r"(r[3]) : "r"(a));
}
// fp32-accumulator HMMA
__device__ __forceinline__ void mma16816(float c[4], const unsigned a[4], const unsigned b[2]) {
    asm volatile(
        "mma.sync.aligned.m16n8k16.row.col.f32.f16.f16.f32 "
        "{%0,%1,%2,%3}, {%4,%5,%6,%7}, {%8,%9}, {%0,%1,%2,%3};\n"
        : "+f"(c[0]), "+f"(c[1]), "+f"(c[2]), "+f"(c[3])
        : "r"(a[0]), "r"(a[1]), "r"(a[2]), "r"(a[3]), "r"(b[0]), "r"(b[1]));
}
// fp16-accumulator HMMA (GEMM1; same issue rate, halves acc registers)
__device__ __forceinline__ void mma16816h(unsigned c[2], const unsigned a[4], const unsigned b[2]) {
    asm volatile(
        "mma.sync.aligned.m16n8k16.row.col.f16.f16.f16.f16 "
        "{%0,%1}, {%2,%3,%4,%5}, {%6,%7}, {%0,%1};\n"
        : "+r"(c[0]), "+r"(c[1])
        : "r"(a[0]), "r"(a[1]), "r"(a[2]), "r"(a[3]), "r"(b[0]), "r"(b[1]));
}

// sharp(x) = sigmoid(10x-5) + sigmoid(-10x-5)
__device__ __forceinline__ float sharp_fn(float x) {
    const float E = 148.4131591f;      // e^5
    const float E2p1 = 22027.4658f;    // e^10 + 1
    float u = __expf(10.f * x);
    float eu = E * u;
    float num = fmaf(eu, u, fmaf(2.f, u, E));
    float den = fmaf(eu, u, fmaf(E2p1, u, E));
    return __fdividef(num, den);
}

// fill: 256 rows x 64 cols fp16; pg = per-thread global ptr, sdst = dst + thread smem const
template <int LDB>
__device__ __forceinline__ void fillB2p(const __half* __restrict__ pg, uint32_t sdst) {
#pragma unroll
    for (int it = 0; it < 8; ++it)
        cp16(sdst + it * 4096, pg + (size_t)it * 32 * LDB);
}

// ---- merged prep kernel ----
__global__ void prep_kernel(const float* __restrict__ key, const float* __restrict__ val) {
    __shared__ float tile[32][33];
    __shared__ float ws[8];
    __shared__ float sinv;
    const int tid = threadIdx.x;
    if (blockIdx.x < 1024) {
        const int ko = (blockIdx.x & 31) * 32;
        const int no = (blockIdx.x >> 5) * 32;
        const int tx = tid & 31, ty = tid >> 5;
#pragma unroll
        for (int j = 0; j < 32; j += 8)
            tile[ty + j][tx] = val[(size_t)(ko + ty + j) * C_DIM + no + tx];
        __syncthreads();
#pragma unroll
        for (int j = 0; j < 32; j += 8)
            g_Vt[(size_t)(no + ty + j) * C_DIM + ko + tx] = __float2half(tile[tx][ty + j]);
    } else {
        const int r = blockIdx.x - 1024;
        const float* kr = key + (size_t)r * D_DIM;
        float v[2];
        float ss = 0.f;
#pragma unroll
        for (int i = 0; i < 2; ++i) { v[i] = kr[tid + i * 256]; ss += v[i] * v[i]; }
#pragma unroll
        for (int o = 16; o > 0; o >>= 1) ss += __shfl_down_sync(0xffffffffu, ss, o);
        if ((tid & 31) == 0) ws[tid >> 5] = ss;
        __syncthreads();
        if (tid == 0) {
            float s = 0.f;
#pragma unroll
            for (int j = 0; j < 8; ++j) s += ws[j];
            sinv = rsqrtf(s + 1e-12f);
        }
        __syncthreads();
        const float iv = sinv;
#pragma unroll
        for (int i = 0; i < 2; ++i)
            g_Kh[(size_t)r * D_DIM + tid + i * 256] = __float2half(v[i] * iv);
    }
}

// ---- fused main kernel: 256 threads, 8 warps, warp tile 32x64 ----
__global__ __launch_bounds__(NTHREADS, 1)
void fused_kv_kernel(const float* __restrict__ query, float* __restrict__ out) {
    extern __shared__ char smem[];
    const uint32_t sb = smem_u32(smem);
    float* red = (float*)(smem + REDOFF);
    float* inv = (float*)(smem + INVOFF);

    const int tid  = threadIdx.x;
    const int lane = tid & 31;
    const int wid  = tid >> 5;
    const int wpar = wid & 1;           // fill-stagger parity
    const int wm   = wid >> 2;
    const int wn   = wid & 3;
    const int g    = lane >> 2;
    const int tig  = lane & 3;
    const int lrow = lane & 15;
    const int hs   = lane >> 4;
    const int row0 = blockIdx.x * M_TILE;

    // precomputed LDSM address components
    uint32_t koff[4], arow[2], brow[4];
    {
        const uint32_t xr = (uint32_t)(lrow & 7) * 16u;
#pragma unroll
        for (int ks = 0; ks < 4; ++ks)
            koff[ks] = ((uint32_t)(ks * 32 + hs * 16)) ^ xr;
#pragma unroll
        for (int mi = 0; mi < 2; ++mi)
            arow[mi] = (uint32_t)(wm * 32 + mi * 16 + lrow) * 128u;
#pragma unroll
        for (int pr = 0; pr < 4; ++pr)
            brow[pr] = (uint32_t)(wn * 64 + pr * 16 + lrow) * 128u;
    }
    const uint32_t fr0 = (uint32_t)(tid >> 3);
    const uint32_t fc  = (uint32_t)(tid & 7);
    const uint32_t fs0 = fr0 * 128u + ((fc * 16u) ^ ((fr0 & 7u) * 16u));
    const uint32_t gofs1 = fr0 * D_DIM + fc * 8;
    const uint32_t gofs2 = fr0 * C_DIM + fc * 8;

    // EARLY: GEMM1 stage-0 fill (latency covered by Q-load phase)
    fillB2p<D_DIM>(g_Kh + gofs1, sb + WOFF + fs0);
    CP_COMMIT();

    // ---- Step 0: load RAW q -> fp16 smem (swizzled) + 1/||q|| ----
    {
        const int r = tid >> 2;
        const int p = tid & 3;
        const float* qrow = query + (size_t)(row0 + r) * D_DIM + p * 128;
        float ss = 0.f;
#pragma unroll
        for (int q = 0; q < 2; ++q) {
            char* pb = smem + QOFF + (2 * p + q) * 8192;
#pragma unroll 4
            for (int j = 0; j < 64; j += 4) {
                float4 v = *(const float4*)(qrow + q * 64 + j);
                ss += v.x * v.x + v.y * v.y + v.z * v.z + v.w * v.w;
                int b = r * 128 + j * 2;
                *(__half2*)(pb + SWZ(b))     = __floats2half2_rn(v.x, v.y);
                *(__half2*)(pb + SWZ(b + 4)) = __floats2half2_rn(v.z, v.w);
            }
        }
        red[tid] = ss;
        __syncthreads();
        if (tid < M_TILE)
            inv[tid] = rsqrtf(red[tid * 4] + red[tid * 4 + 1] +
                              red[tid * 4 + 2] + red[tid * 4 + 3] + 1e-12f);
        __syncthreads();
    }
    float qa[4];
#pragma unroll
    for (int j = 0; j < 4; ++j) qa[j] = inv[wm * 32 + j * 8 + g];
    __syncthreads();
    if (tid < M_TILE) red[tid] = 0.f;

    // ---- GEMM1: W = sharp(qinv * (q @ Kn^T)); fp16 acc, staggered fills ----
    {
        unsigned acch[2][8][2];
        float rs[2][2] = {{0.f, 0.f}, {0.f, 0.f}};

#pragma unroll 1
        for (int t = 0; t < 32; ++t) {
            const int nc = t >> 3, kc = t & 7;
            CP_WAIT0();
            __syncthreads();
            const bool dofill = (t + 1 < 32);
            const int u = t + 1;
            const uint32_t fdst = (u & 1) ? (uint32_t)SBOFF
                                          : (uint32_t)(WOFF + ((u >> 3) << 15));
            const __half* fsrc = g_Kh + ((size_t)(u >> 3) * 256) * D_DIM + (u & 7) * 64 + gofs1;
            // even warps fill first (odd warps proceed straight to MMAs)
            if (dofill && wpar == 0) {
                fillB2p<D_DIM>(fsrc, sb + fdst + fs0);
                CP_COMMIT();
            }
            if (kc == 0) {
#pragma unroll
                for (int mi = 0; mi < 2; ++mi)
#pragma unroll
                    for (int ni = 0; ni < 8; ++ni) {
                        acch[mi][ni][0] = 0u;
                        acch[mi][ni][1] = 0u;
                    }
            }
            const uint32_t sB = sb + ((t & 1) ? (uint32_t)SBOFF
                                              : (uint32_t)(WOFF + (nc << 15)));
            const uint32_t sA = sb + QOFF + kc * 8192;

            unsigned af[2][2][4];
#pragma unroll
            for (int mi = 0; mi < 2; ++mi)
                ldsm4(af[0][mi], sA + arow[mi] + koff[0]);
#pragma unroll
            for (int ks = 0; ks < 4; ++ks) {
                const int cur = ks & 1;
                if (ks == 2 && dofill && wpar == 1) {
                    // odd warps fill mid-iteration (even warps are now doing MMAs)
                    fillB2p<D_DIM>(fsrc, sb + fdst + fs0);
                    CP_COMMIT();
                }
                if (ks < 3)
#pragma unroll
                    for (int mi = 0; mi < 2; ++mi)
                        ldsm4(af[cur ^ 1][mi], sA + arow[mi] + koff[ks + 1]);
                unsigned b[8][2];
#pragma unroll
                for (int pr = 0; pr < 4; ++pr) {
                    unsigned r4[4];
                    ldsm4(r4, sB + brow[pr] + koff[ks]);
                    b[pr * 2][0] = r4[0]; b[pr * 2 + 1][0] = r4[1];
                    b[pr * 2][1] = r4[2]; b[pr * 2 + 1][1] = r4[3];
                }
#pragma unroll
                for (int mi = 0; mi < 2; ++mi)
#pragma unroll
                    for (int ni = 0; ni < 8; ++ni)
                        mma16816h(acch[mi][ni], af[cur][mi], b[ni]);
            }
            if (kc == 7) {
#pragma unroll
                for (int mi = 0; mi < 2; ++mi) {
#pragma unroll
                    for (int ni = 0; ni < 8; ++ni) {
                        int rr = wm * 32 + mi * 16 + g;
                        int cc = nc * 256 + wn * 64 + ni * 8 + tig * 2;
                        int panel = cc >> 6, c6 = cc & 63;
                        char* base = smem + WOFF + panel * 8192;
                        float2 f0 = __half22float2(*(__half2*)&acch[mi][ni][0]);
                        float2 f1 = __half22float2(*(__half2*)&acch[mi][ni][1]);
                        float w0 = sharp_fn(f0.x * qa[mi * 2]);
                        float w1 = sharp_fn(f0.y * qa[mi * 2]);
                        float w2 = sharp_fn(f1.x * qa[mi * 2 + 1]);
                        float w3 = sharp_fn(f1.y * qa[mi * 2 + 1]);
                        rs[mi][0] += w0 + w1;
                        rs[mi][1] += w2 + w3;
                        *(__half2*)(base + SWZ(rr * 128 + c6 * 2)) = __floats2half2_rn(w0, w1);
                        *(__half2*)(base + SWZ((rr + 8) * 128 + c6 * 2)) = __floats2half2_rn(w2, w3);
                    }
                }
            }
        }
        // OVERLAP: GEMM2 stage-0 fill (overwrites Q panels 0-3; stragglers read only panel 7)
        fillB2p<C_DIM>(g_Vt + gofs2, sb + QOFF + fs0);
        CP_COMMIT();

        atomicAdd(&red[wm * 32 + g],       rs[0][0]);
        atomicAdd(&red[wm * 32 + g + 8],   rs[0][1]);
        atomicAdd(&red[wm * 32 + 16 + g],  rs[1][0]);
        atomicAdd(&red[wm * 32 + 24 + g],  rs[1][1]);
        __syncthreads();
        if (tid < M_TILE) inv[tid] = 1.f / red[tid];
        __syncthreads();
    }

    // ---- GEMM2: out = (1/rowsum) * W @ val; fp32 acc, staggered fills ----
    {
        float acc[2][8][4];
        uint32_t s0 = QOFF, s1 = QOFF + ST2SZ, s2 = SBOFF;
        fillB2p<C_DIM>(g_Vt + 64 + gofs2, sb + s1 + fs0);
        CP_COMMIT();

#pragma unroll 1
        for (int t = 0; t < 64; ++t) {
            const int nc = t >> 4, kc = t & 15;
            CP_WAIT1();
            __syncthreads();
            const int u = t + 2;
            const bool dofill = (u < 64);
            const __half* fsrc = g_Vt + ((size_t)(u >> 4) * 256) * C_DIM + (u & 15) * 64 + gofs2;
            if (dofill && wpar == 0) {
                fillB2p<C_DIM>(fsrc, sb + s2 + fs0);
                CP_COMMIT();
            }
            if (kc == 0) {
#pragma unroll
                for (int mi = 0; mi < 2; ++mi)
#pragma unroll
                    for (int ni = 0; ni < 8; ++ni)
#pragma unroll
                        for (int e = 0; e < 4; ++e) acc[mi][ni][e] = 0.f;
            }
            const uint32_t sB = sb + s0;
            const uint32_t sA = sb + WOFF + kc * 8192;

            unsigned af[2][2][4];
#pragma unroll
            for (int mi = 0; mi < 2; ++mi)
                ldsm4(af[0][mi], sA + arow[mi] + koff[0]);
#pragma unroll
            for (int ks = 0; ks < 4; ++ks) {
                const int cur = ks & 1;
                if (ks == 2 && dofill && wpar == 1) {
                    fillB2p<C_DIM>(fsrc, sb + s2 + fs0);
                    CP_COMMIT();
                }
                if (ks < 3)
#pragma unroll
                    for (int mi = 0; mi < 2; ++mi)
                        ldsm4(af[cur ^ 1][mi], sA + arow[mi] + koff[ks + 1]);
                unsigned b[8][2];
#pragma unroll
                for (int pr = 0; pr < 4; ++pr) {
                    unsigned r4[4];
                    ldsm4(r4, sB + brow[pr] + koff[ks]);
                    b[pr * 2][0] = r4[0]; b[pr * 2 + 1][0] = r4[1];
                    b[pr * 2][1] = r4[2]; b[pr * 2 + 1][1] = r4[3];
                }
#pragma unroll
                for (int mi = 0; mi < 2; ++mi)
#pragma unroll
                    for (int ni = 0; ni < 8; ++ni)
                        mma16816(acc[mi][ni], af[cur][mi], b[ni]);
            }
            if (kc == 15) {
#pragma unroll
                for (int mi = 0; mi < 2; ++mi) {
#pragma unroll
                    for (int ni = 0; ni < 8; ++ni) {
                        int rr = wm * 32 + mi * 16 + g;
                        int cc = nc * 256 + wn * 64 + ni * 8 + tig * 2;
                        float i0 = inv[rr], i8 = inv[rr + 8];
                        *(float2*)(out + (size_t)(row0 + rr) * C_DIM + cc) =
                            make_float2(acc[mi][ni][0] * i0, acc[mi][ni][1] * i0);
                        *(float2*)(out + (size_t)(row0 + rr + 8) * C_DIM + cc) =
                            make_float2(acc[mi][ni][2] * i8, acc[mi][ni][3] * i8);
                    }
                }
            }
            const uint32_t tmp = s0; s0 = s1; s1 = s2; s2 = tmp;
        }
    }
}

// ---------------------------------------------------------------------------
extern "C" void kernel_launch(void* const* d_in, const int* in_sizes, int n_in,
                              void* d_out, int out_size) {
    const float* query = (const float*)d_in[0];
    const float* key   = (const float*)d_in[1];
    const float* val   = (const float*)d_in[2];
    float* out = (float*)d_out;

    const int B = in_sizes[0] / D_DIM;

    prep_kernel<<<2048, 256>>>(key, val);

    cudaFuncSetAttribute(fused_kv_kernel,
                         cudaFuncAttributeMaxDynamicSharedMemorySize, SMEM_BYTES);
    fused_kv_kernel<<<B / M_TILE, NTHREADS, SMEM_BYTES>>>(query, out);
}